// round 1
// baseline (speedup 1.0000x reference)
#include <cuda_runtime.h>
#include <math.h>

#define N_NODES 20000
#define N_EDGES 640000
#define E_TOT   660000          // + self loops
#define H1      4
#define C       128
#define HC1     (H1 * C)        // 512

// ---------------- scratch (no allocations allowed) ----------------
__device__ float g_h1[N_NODES * HC1];
__device__ float g_acc1[N_NODES * HC1];
__device__ float g_as1[N_NODES * H1];
__device__ float g_ad1[N_NODES * H1];
__device__ float g_m1[N_NODES * H1];
__device__ float g_den1[N_NODES * H1];
__device__ float g_x2[N_NODES * C];
__device__ float g_h2[N_NODES * C];
__device__ float g_acc2[N_NODES * C];
__device__ float g_as2[N_NODES];
__device__ float g_ad2[N_NODES];
__device__ float g_m2[N_NODES];
__device__ float g_den2[N_NODES];

// ---------------- GEMM: C[M,N] = A[M,K] * B[K,N], BM=BN=64, BK=16 ----------------
__global__ __launch_bounds__(256) void sgemm_kernel(
    const float* __restrict__ A, const float* __restrict__ B,
    float* __restrict__ Cmat, int M, int N, int K)
{
    __shared__ float As[16][68];   // padded, rows 16B-aligned (272B)
    __shared__ float Bs[16][64];

    const int tid = threadIdx.x;
    const int tx = tid & 15;        // 0..15
    const int ty = tid >> 4;        // 0..15
    const int rowBase = blockIdx.y * 64;
    const int colBase = blockIdx.x * 64;

    float acc[4][4];
#pragma unroll
    for (int i = 0; i < 4; i++)
#pragma unroll
        for (int j = 0; j < 4; j++) acc[i][j] = 0.f;

    for (int k0 = 0; k0 < K; k0 += 16) {
        // load A tile 64x16 (transposed into As[k][row])
#pragma unroll
        for (int i = tid; i < 64 * 16; i += 256) {
            int r = i >> 4, c = i & 15;
            int gr = rowBase + r;
            As[c][r] = (gr < M) ? A[(size_t)gr * K + k0 + c] : 0.f;
        }
        // load B tile 16x64
#pragma unroll
        for (int i = tid; i < 16 * 64; i += 256) {
            int r = i >> 6, c = i & 63;
            Bs[r][c] = B[(size_t)(k0 + r) * N + colBase + c];
        }
        __syncthreads();
#pragma unroll
        for (int kk = 0; kk < 16; kk++) {
            float4 a4 = *(const float4*)&As[kk][ty * 4];
            float4 b4 = *(const float4*)&Bs[kk][tx * 4];
            float av[4] = {a4.x, a4.y, a4.z, a4.w};
            float bv[4] = {b4.x, b4.y, b4.z, b4.w};
#pragma unroll
            for (int i = 0; i < 4; i++)
#pragma unroll
                for (int j = 0; j < 4; j++) acc[i][j] += av[i] * bv[j];
        }
        __syncthreads();
    }
#pragma unroll
    for (int i = 0; i < 4; i++) {
        int gr = rowBase + ty * 4 + i;
        if (gr < M) {
            float4 o = make_float4(acc[i][0], acc[i][1], acc[i][2], acc[i][3]);
            *(float4*)&Cmat[(size_t)gr * N + colBase + tx * 4] = o;
        }
    }
}

// ---------------- per-(node,head) attention logits: warp dot products ----------------
__global__ __launch_bounds__(256) void alphas_kernel(
    const float* __restrict__ h, const float* __restrict__ a_src,
    const float* __restrict__ a_dst, float* __restrict__ as_out,
    float* __restrict__ ad_out, int NH, int H)
{
    int w = (blockIdx.x * blockDim.x + threadIdx.x) >> 5;
    int lane = threadIdx.x & 31;
    if (w >= NH) return;
    int hh = w % H;
    float4 x = ((const float4*)(h + (size_t)w * C))[lane];
    float4 u = ((const float4*)(a_src + hh * C))[lane];
    float4 v = ((const float4*)(a_dst + hh * C))[lane];
    float ss = x.x * u.x + x.y * u.y + x.z * u.z + x.w * u.w;
    float sd = x.x * v.x + x.y * v.y + x.z * v.z + x.w * v.w;
#pragma unroll
    for (int off = 16; off > 0; off >>= 1) {
        ss += __shfl_down_sync(0xffffffff, ss, off);
        sd += __shfl_down_sync(0xffffffff, sd, off);
    }
    if (lane == 0) { as_out[w] = ss; ad_out[w] = sd; }
}

// ---------------- init m/-inf, den/acc = 0 ----------------
__global__ __launch_bounds__(256) void init_kernel(
    float* __restrict__ m, float* __restrict__ den, float* __restrict__ acc,
    int NH, int NHC)
{
    int i = blockIdx.x * blockDim.x + threadIdx.x;
    if (i < NH) { m[i] = -INFINITY; den[i] = 0.f; }
    if (i < NHC) acc[i] = 0.f;
}

__device__ __forceinline__ void atomicMaxFloat(float* addr, float val)
{
    int old = __float_as_int(*addr);
    while (__int_as_float(old) < val) {
        int assumed = old;
        old = atomicCAS((int*)addr, assumed, __float_as_int(val));
        if (old == assumed) break;
    }
}

// ---------------- edge pass 1: segment max ----------------
template <int H>
__global__ __launch_bounds__(256) void edge_max_kernel(
    const int* __restrict__ ei, const float* __restrict__ as_v,
    const float* __restrict__ ad_v, float* __restrict__ m)
{
    int i = blockIdx.x * blockDim.x + threadIdx.x;
    if (i >= E_TOT) return;
    int s, d;
    if (i < N_EDGES) { s = ei[i]; d = ei[N_EDGES + i]; }
    else { s = d = i - N_EDGES; }
#pragma unroll
    for (int hh = 0; hh < H; hh++) {
        float e = as_v[s * H + hh] + ad_v[d * H + hh];
        e = e > 0.f ? e : 0.2f * e;   // leaky_relu(0.2)
        atomicMaxFloat(&m[d * H + hh], e);
    }
}

// ---------------- edge pass 2: exp + weighted accumulate (one warp / edge) ----------------
template <int H>
__global__ __launch_bounds__(256) void edge_acc_kernel(
    const int* __restrict__ ei, const float* __restrict__ as_v,
    const float* __restrict__ ad_v, const float* __restrict__ m,
    const float* __restrict__ hfeat, float* __restrict__ den,
    float* __restrict__ acc)
{
    int w = (blockIdx.x * blockDim.x + threadIdx.x) >> 5;
    int lane = threadIdx.x & 31;
    if (w >= E_TOT) return;
    int s, d;
    if (w < N_EDGES) { s = ei[w]; d = ei[N_EDGES + w]; }
    else { s = d = w - N_EDGES; }
#pragma unroll
    for (int hh = 0; hh < H; hh++) {
        float e = as_v[s * H + hh] + ad_v[d * H + hh];
        e = e > 0.f ? e : 0.2f * e;
        float p = __expf(e - m[d * H + hh]);
        if (lane == 0) atomicAdd(&den[d * H + hh], p);
        float4 hv = ((const float4*)(hfeat + ((size_t)s * H + hh) * C))[lane];
        float4 addv = make_float4(p * hv.x, p * hv.y, p * hv.z, p * hv.w);
        atomicAdd(((float4*)(acc + ((size_t)d * H + hh) * C)) + lane, addv);
    }
}

// ---------------- finalize layer 1: mean over heads, bias, ELU -> x2 ----------------
__global__ __launch_bounds__(256) void finalize1_kernel(
    const float* __restrict__ acc, const float* __restrict__ den,
    const float* __restrict__ b, float* __restrict__ x2)
{
    int i = blockIdx.x * blockDim.x + threadIdx.x;
    if (i >= N_NODES * C) return;
    int n = i / C, c = i % C;
    float v = 0.f;
#pragma unroll
    for (int hh = 0; hh < H1; hh++)
        v += acc[((size_t)n * H1 + hh) * C + c] / den[n * H1 + hh];
    v = v * (1.f / H1) + b[c];
    x2[i] = v > 0.f ? v : expm1f(v);
}

// ---------------- finalize layer 2: bias, ELU -> out ----------------
__global__ __launch_bounds__(256) void finalize2_kernel(
    const float* __restrict__ acc, const float* __restrict__ den,
    const float* __restrict__ b, float* __restrict__ out)
{
    int i = blockIdx.x * blockDim.x + threadIdx.x;
    if (i >= N_NODES * C) return;
    int n = i / C, c = i % C;
    float v = acc[i] / den[n] + b[c];
    out[i] = v > 0.f ? v : expm1f(v);
}

// ---------------- launch ----------------
extern "C" void kernel_launch(void* const* d_in, const int* in_sizes, int n_in,
                              void* d_out, int out_size)
{
    const float* x      = (const float*)d_in[0];
    const float* W1     = (const float*)d_in[1];
    const float* a_src1 = (const float*)d_in[2];
    const float* a_dst1 = (const float*)d_in[3];
    const float* b1     = (const float*)d_in[4];
    const float* W2     = (const float*)d_in[5];
    const float* a_src2 = (const float*)d_in[6];
    const float* a_dst2 = (const float*)d_in[7];
    const float* b2     = (const float*)d_in[8];
    const int*   ei     = (const int*)d_in[9];
    float* out = (float*)d_out;

    float *h1, *acc1, *as1, *ad1, *m1, *den1;
    float *x2, *h2, *acc2, *as2, *ad2, *m2, *den2;
    cudaGetSymbolAddress((void**)&h1,   g_h1);
    cudaGetSymbolAddress((void**)&acc1, g_acc1);
    cudaGetSymbolAddress((void**)&as1,  g_as1);
    cudaGetSymbolAddress((void**)&ad1,  g_ad1);
    cudaGetSymbolAddress((void**)&m1,   g_m1);
    cudaGetSymbolAddress((void**)&den1, g_den1);
    cudaGetSymbolAddress((void**)&x2,   g_x2);
    cudaGetSymbolAddress((void**)&h2,   g_h2);
    cudaGetSymbolAddress((void**)&acc2, g_acc2);
    cudaGetSymbolAddress((void**)&as2,  g_as2);
    cudaGetSymbolAddress((void**)&ad2,  g_ad2);
    cudaGetSymbolAddress((void**)&m2,   g_m2);
    cudaGetSymbolAddress((void**)&den2, g_den2);

    const int TPB = 256;
    dim3 gemm1_grid(HC1 / 64, (N_NODES + 63) / 64);
    dim3 gemm2_grid(C / 64,   (N_NODES + 63) / 64);
    int nh1 = N_NODES * H1, nhc1 = N_NODES * HC1;
    int nh2 = N_NODES,      nhc2 = N_NODES * C;

    // ---- layer 1 ----
    sgemm_kernel<<<gemm1_grid, TPB>>>(x, W1, h1, N_NODES, HC1, C);
    alphas_kernel<<<(nh1 * 32 + TPB - 1) / TPB, TPB>>>(h1, a_src1, a_dst1, as1, ad1, nh1, H1);
    init_kernel<<<(nhc1 + TPB - 1) / TPB, TPB>>>(m1, den1, acc1, nh1, nhc1);
    edge_max_kernel<H1><<<(E_TOT + TPB - 1) / TPB, TPB>>>(ei, as1, ad1, m1);
    edge_acc_kernel<H1><<<((size_t)E_TOT * 32 + TPB - 1) / TPB, TPB>>>(ei, as1, ad1, m1, h1, den1, acc1);
    finalize1_kernel<<<(nhc2 + TPB - 1) / TPB, TPB>>>(acc1, den1, b1, x2);

    // ---- layer 2 ----
    sgemm_kernel<<<gemm2_grid, TPB>>>(x2, W2, h2, N_NODES, C, C);
    alphas_kernel<<<(nh2 * 32 + TPB - 1) / TPB, TPB>>>(h2, a_src2, a_dst2, as2, ad2, nh2, 1);
    init_kernel<<<(nhc2 + TPB - 1) / TPB, TPB>>>(m2, den2, acc2, nh2, nhc2);
    edge_max_kernel<1><<<(E_TOT + TPB - 1) / TPB, TPB>>>(ei, as2, ad2, m2);
    edge_acc_kernel<1><<<((size_t)E_TOT * 32 + TPB - 1) / TPB, TPB>>>(ei, as2, ad2, m2, h2, den2, acc2);
    finalize2_kernel<<<(nhc2 + TPB - 1) / TPB, TPB>>>(acc2, den2, b2, out);
}

// round 3
// speedup vs baseline: 1.6827x; 1.6827x over previous
#include <cuda_runtime.h>
#include <math.h>

#define N_NODES 20000
#define N_EDGES 640000
#define E_TOT   660000          // + self loops
#define H1      4
#define C       128
#define HC1     (H1 * C)        // 512

// ---------------- scratch (no allocations allowed) ----------------
__device__ float g_h1[N_NODES * HC1];
__device__ float g_acc1[N_NODES * HC1];
__device__ float g_as1[N_NODES * H1];
__device__ float g_ad1[N_NODES * H1];
__device__ float g_x2[N_NODES * C];
__device__ float g_h2[N_NODES * C];
__device__ float g_as2[N_NODES];
__device__ float g_ad2[N_NODES];
__device__ int   g_rowptr[N_NODES + 1];
__device__ int   g_cursor[N_NODES];
__device__ int   g_cnt[N_NODES];
__device__ int   g_csrc[E_TOT];

// ================= CSR build =================
__global__ __launch_bounds__(256) void zero_cnt_kernel(int* __restrict__ cnt)
{
    int i = blockIdx.x * blockDim.x + threadIdx.x;
    if (i < N_NODES) cnt[i] = 0;
}

__global__ __launch_bounds__(256) void count_kernel(
    const int* __restrict__ ei, int* __restrict__ cnt)
{
    int i = blockIdx.x * blockDim.x + threadIdx.x;
    if (i >= E_TOT) return;
    int d = (i < N_EDGES) ? ei[N_EDGES + i] : (i - N_EDGES);
    atomicAdd(&cnt[d], 1);
}

// single-block exclusive scan over 20000 counts (1024 threads, chunk=20)
__global__ __launch_bounds__(1024) void scan_kernel(
    const int* __restrict__ cnt, int* __restrict__ rowptr, int* __restrict__ cursor)
{
    __shared__ int part[1024];
    const int t = threadIdx.x;
    const int CHUNK = 20;  // 1024*20 = 20480 >= 20000
    int base = t * CHUNK;
    int s = 0;
#pragma unroll
    for (int k = 0; k < CHUNK; k++) {
        int i = base + k;
        if (i < N_NODES) s += cnt[i];
    }
    part[t] = s;
    __syncthreads();
    // Hillis-Steele inclusive scan
    for (int off = 1; off < 1024; off <<= 1) {
        int v = (t >= off) ? part[t - off] : 0;
        __syncthreads();
        part[t] += v;
        __syncthreads();
    }
    int run = part[t] - s;   // exclusive prefix for this thread's chunk
#pragma unroll
    for (int k = 0; k < CHUNK; k++) {
        int i = base + k;
        if (i < N_NODES) {
            rowptr[i] = run;
            cursor[i] = run;
            run += cnt[i];
        }
    }
    if (t == 1023) rowptr[N_NODES] = part[1023];
}

__global__ __launch_bounds__(256) void scatter_kernel(
    const int* __restrict__ ei, int* __restrict__ cursor, int* __restrict__ csrc)
{
    int i = blockIdx.x * blockDim.x + threadIdx.x;
    if (i >= E_TOT) return;
    int s, d;
    if (i < N_EDGES) { s = ei[i]; d = ei[N_EDGES + i]; }
    else { s = d = i - N_EDGES; }
    int pos = atomicAdd(&cursor[d], 1);
    csrc[pos] = s;
}

// ================= GEMM: C[M,N] = A[M,K]*B[K,N]; BM=BN=128, BK=8, 8x8 microtile =================
__global__ __launch_bounds__(256) void sgemm_kernel(
    const float* __restrict__ A, const float* __restrict__ B,
    float* __restrict__ Cmat, int M, int N, int K)
{
    __shared__ float As[8][132];   // transposed A tile, padded
    __shared__ float Bs[8][128];

    const int tid = threadIdx.x;
    const int tx = tid & 15;        // 0..15 -> 8 cols each
    const int ty = tid >> 4;        // 0..15 -> 8 rows each
    const int rowBase = blockIdx.y * 128;
    const int colBase = blockIdx.x * 128;

    // A load mapping: 2 threads per row, each loads float4 of K
    const int a_row = tid >> 1;           // 0..127
    const int a_col = (tid & 1) * 4;      // 0 or 4
    // B load mapping: 32 threads per row of 128
    const int b_row = tid >> 5;           // 0..7
    const int b_col = (tid & 31) * 4;

    float acc[8][8];
#pragma unroll
    for (int i = 0; i < 8; i++)
#pragma unroll
        for (int j = 0; j < 8; j++) acc[i][j] = 0.f;

    for (int k0 = 0; k0 < K; k0 += 8) {
        int gr = rowBase + a_row;
        float4 av4 = make_float4(0.f, 0.f, 0.f, 0.f);
        if (gr < M) av4 = *(const float4*)&A[(size_t)gr * K + k0 + a_col];
        As[a_col + 0][a_row] = av4.x;
        As[a_col + 1][a_row] = av4.y;
        As[a_col + 2][a_row] = av4.z;
        As[a_col + 3][a_row] = av4.w;
        *(float4*)&Bs[b_row][b_col] = *(const float4*)&B[(size_t)(k0 + b_row) * N + colBase + b_col];
        __syncthreads();
#pragma unroll
        for (int kk = 0; kk < 8; kk++) {
            float a[8], b[8];
            *(float4*)&a[0] = *(const float4*)&As[kk][ty * 8];
            *(float4*)&a[4] = *(const float4*)&As[kk][ty * 8 + 4];
            *(float4*)&b[0] = *(const float4*)&Bs[kk][tx * 8];
            *(float4*)&b[4] = *(const float4*)&Bs[kk][tx * 8 + 4];
#pragma unroll
            for (int i = 0; i < 8; i++)
#pragma unroll
                for (int j = 0; j < 8; j++) acc[i][j] += a[i] * b[j];
        }
        __syncthreads();
    }
#pragma unroll
    for (int i = 0; i < 8; i++) {
        int gr = rowBase + ty * 8 + i;
        if (gr < M) {
            *(float4*)&Cmat[(size_t)gr * N + colBase + tx * 8]     = *(float4*)&acc[i][0];
            *(float4*)&Cmat[(size_t)gr * N + colBase + tx * 8 + 4] = *(float4*)&acc[i][4];
        }
    }
}

// ================= attention logits: warp dot products =================
__global__ __launch_bounds__(256) void alphas_kernel(
    const float* __restrict__ h, const float* __restrict__ a_src,
    const float* __restrict__ a_dst, float* __restrict__ as_out,
    float* __restrict__ ad_out, int NH, int H)
{
    int w = (blockIdx.x * blockDim.x + threadIdx.x) >> 5;
    int lane = threadIdx.x & 31;
    if (w >= NH) return;
    int hh = w % H;
    float4 x = ((const float4*)(h + (size_t)w * C))[lane];
    float4 u = ((const float4*)(a_src + hh * C))[lane];
    float4 v = ((const float4*)(a_dst + hh * C))[lane];
    float ss = x.x * u.x + x.y * u.y + x.z * u.z + x.w * u.w;
    float sd = x.x * v.x + x.y * v.y + x.z * v.z + x.w * v.w;
#pragma unroll
    for (int off = 16; off > 0; off >>= 1) {
        ss += __shfl_down_sync(0xffffffff, ss, off);
        sd += __shfl_down_sync(0xffffffff, sd, off);
    }
    if (lane == 0) { as_out[w] = ss; ad_out[w] = sd; }
}

// ================= gather aggregation, layer 1 (one warp per (dst,head)) =================
__global__ __launch_bounds__(256) void agg1_kernel(
    const int* __restrict__ rowptr, const int* __restrict__ csrc,
    const float* __restrict__ as_v, const float* __restrict__ ad_v,
    const float* __restrict__ hfeat, float* __restrict__ accO)
{
    int w = (blockIdx.x * blockDim.x + threadIdx.x) >> 5;
    int lane = threadIdx.x & 31;
    if (w >= N_NODES * H1) return;
    int n = w >> 2, hh = w & 3;
    int start = rowptr[n], end = rowptr[n + 1];
    float adn = ad_v[n * H1 + hh];

    float4 acc = make_float4(0.f, 0.f, 0.f, 0.f);
    float den = 0.f;
    int s_next = (start < end) ? csrc[start] : 0;
    for (int e = start; e < end; e++) {
        int s = s_next;
        if (e + 1 < end) s_next = csrc[e + 1];
        float l = as_v[s * H1 + hh] + adn;
        l = l > 0.f ? l : 0.2f * l;            // leaky_relu 0.2
        float p = __expf(l);                   // no max-shift needed (bounded logits)
        den += p;
        float4 hv = ((const float4*)(hfeat + ((size_t)s * H1 + hh) * C))[lane];
        acc.x += p * hv.x; acc.y += p * hv.y; acc.z += p * hv.z; acc.w += p * hv.w;
    }
    float inv = 1.f / den;
    float4 o = make_float4(acc.x * inv, acc.y * inv, acc.z * inv, acc.w * inv);
    ((float4*)(accO + ((size_t)n * H1 + hh) * C))[lane] = o;
}

// ================= finalize layer 1: mean heads + bias + ELU -> x2 =================
__global__ __launch_bounds__(256) void finalize1_kernel(
    const float* __restrict__ acc, const float* __restrict__ b,
    float* __restrict__ x2)
{
    int i = blockIdx.x * blockDim.x + threadIdx.x;
    if (i >= N_NODES * C) return;
    int n = i / C, c = i % C;
    float v = 0.f;
#pragma unroll
    for (int hh = 0; hh < H1; hh++)
        v += acc[((size_t)n * H1 + hh) * C + c];
    v = v * 0.25f + b[c];
    x2[i] = v > 0.f ? v : expm1f(v);
}

// ================= gather aggregation + finalize, layer 2 (one warp per node) =================
__global__ __launch_bounds__(256) void agg2_kernel(
    const int* __restrict__ rowptr, const int* __restrict__ csrc,
    const float* __restrict__ as_v, const float* __restrict__ ad_v,
    const float* __restrict__ hfeat, const float* __restrict__ b,
    float* __restrict__ out)
{
    int n = (blockIdx.x * blockDim.x + threadIdx.x) >> 5;
    int lane = threadIdx.x & 31;
    if (n >= N_NODES) return;
    int start = rowptr[n], end = rowptr[n + 1];
    float adn = ad_v[n];

    float4 acc = make_float4(0.f, 0.f, 0.f, 0.f);
    float den = 0.f;
    int s_next = (start < end) ? csrc[start] : 0;
    for (int e = start; e < end; e++) {
        int s = s_next;
        if (e + 1 < end) s_next = csrc[e + 1];
        float l = as_v[s] + adn;
        l = l > 0.f ? l : 0.2f * l;
        float p = __expf(l);
        den += p;
        float4 hv = ((const float4*)(hfeat + (size_t)s * C))[lane];
        acc.x += p * hv.x; acc.y += p * hv.y; acc.z += p * hv.z; acc.w += p * hv.w;
    }
    float inv = 1.f / den;
    float4 bb = ((const float4*)b)[lane];
    float vx = acc.x * inv + bb.x;
    float vy = acc.y * inv + bb.y;
    float vz = acc.z * inv + bb.z;
    float vw = acc.w * inv + bb.w;
    float4 o;
    o.x = vx > 0.f ? vx : expm1f(vx);
    o.y = vy > 0.f ? vy : expm1f(vy);
    o.z = vz > 0.f ? vz : expm1f(vz);
    o.w = vw > 0.f ? vw : expm1f(vw);
    ((float4*)(out + (size_t)n * C))[lane] = o;
}

// ---------------- launch ----------------
extern "C" void kernel_launch(void* const* d_in, const int* in_sizes, int n_in,
                              void* d_out, int out_size)
{
    const float* x      = (const float*)d_in[0];
    const float* W1     = (const float*)d_in[1];
    const float* a_src1 = (const float*)d_in[2];
    const float* a_dst1 = (const float*)d_in[3];
    const float* b1     = (const float*)d_in[4];
    const float* W2     = (const float*)d_in[5];
    const float* a_src2 = (const float*)d_in[6];
    const float* a_dst2 = (const float*)d_in[7];
    const float* b2     = (const float*)d_in[8];
    const int*   ei     = (const int*)d_in[9];
    float* out = (float*)d_out;

    float *h1, *acc1, *as1, *ad1, *x2, *h2, *as2, *ad2;
    int *rowptr, *cursor, *cnt, *csrc;
    cudaGetSymbolAddress((void**)&h1,     g_h1);
    cudaGetSymbolAddress((void**)&acc1,   g_acc1);
    cudaGetSymbolAddress((void**)&as1,    g_as1);
    cudaGetSymbolAddress((void**)&ad1,    g_ad1);
    cudaGetSymbolAddress((void**)&x2,     g_x2);
    cudaGetSymbolAddress((void**)&h2,     g_h2);
    cudaGetSymbolAddress((void**)&as2,    g_as2);
    cudaGetSymbolAddress((void**)&ad2,    g_ad2);
    cudaGetSymbolAddress((void**)&rowptr, g_rowptr);
    cudaGetSymbolAddress((void**)&cursor, g_cursor);
    cudaGetSymbolAddress((void**)&cnt,    g_cnt);
    cudaGetSymbolAddress((void**)&csrc,   g_csrc);

    const int TPB = 256;

    // ---- CSR build (shared by both layers) ----
    zero_cnt_kernel<<<(N_NODES + TPB - 1) / TPB, TPB>>>(cnt);
    count_kernel<<<(E_TOT + TPB - 1) / TPB, TPB>>>(ei, cnt);
    scan_kernel<<<1, 1024>>>(cnt, rowptr, cursor);
    scatter_kernel<<<(E_TOT + TPB - 1) / TPB, TPB>>>(ei, cursor, csrc);

    // ---- layer 1 ----
    dim3 g1(HC1 / 128, (N_NODES + 127) / 128);
    sgemm_kernel<<<g1, TPB>>>(x, W1, h1, N_NODES, HC1, C);
    int nh1 = N_NODES * H1;
    alphas_kernel<<<(nh1 * 32 + TPB - 1) / TPB, TPB>>>(h1, a_src1, a_dst1, as1, ad1, nh1, H1);
    agg1_kernel<<<(nh1 * 32 + TPB - 1) / TPB, TPB>>>(rowptr, csrc, as1, ad1, h1, acc1);
    finalize1_kernel<<<(N_NODES * C + TPB - 1) / TPB, TPB>>>(acc1, b1, x2);

    // ---- layer 2 ----
    dim3 g2(C / 128, (N_NODES + 127) / 128);
    sgemm_kernel<<<g2, TPB>>>(x2, W2, h2, N_NODES, C, C);
    alphas_kernel<<<(N_NODES * 32 + TPB - 1) / TPB, TPB>>>(h2, a_src2, a_dst2, as2, ad2, N_NODES, 1);
    agg2_kernel<<<(N_NODES * 32 + TPB - 1) / TPB, TPB>>>(rowptr, csrc, as2, ad2, h2, b2, out);
}

// round 4
// speedup vs baseline: 1.8027x; 1.0713x over previous
#include <cuda_runtime.h>
#include <cuda_fp16.h>
#include <math.h>

#define N_NODES 20000
#define N_EDGES 640000
#define E_TOT   660000          // + self loops
#define H1      4
#define C       128
#define HC1     (H1 * C)        // 512

// ---------------- scratch (no allocations allowed) ----------------
__device__ __half g_h1h[N_NODES * HC1];
__device__ __half g_h2h[N_NODES * C];
__device__ float  g_as1[N_NODES * H1];
__device__ float  g_ad1[N_NODES * H1];
__device__ float  g_x2[N_NODES * C];
__device__ float  g_as2[N_NODES];
__device__ float  g_ad2[N_NODES];
__device__ float  g_was1[C * H1];
__device__ float  g_wad1[C * H1];
__device__ float  g_was2[C];
__device__ float  g_wad2[C];
__device__ int    g_rowptr[N_NODES + 1];
__device__ int    g_cursor[N_NODES];
__device__ int    g_cnt[N_NODES];
__device__ int    g_csrc[E_TOT];

// ================= weight folding (+ cnt zero) =================
// w_as1[k,h] = sum_c W1[k, h*C+c]*a_src1[h,c]  (likewise dst, layer 2)
__global__ __launch_bounds__(256) void wfold_kernel(
    const float* __restrict__ W1, const float* __restrict__ as1,
    const float* __restrict__ ad1, const float* __restrict__ W2,
    const float* __restrict__ as2, const float* __restrict__ ad2,
    float* __restrict__ w_as1, float* __restrict__ w_ad1,
    float* __restrict__ w_as2, float* __restrict__ w_ad2,
    int* __restrict__ cnt)
{
    int gid = blockIdx.x * blockDim.x + threadIdx.x;
    if (gid < N_NODES) cnt[gid] = 0;
    int w = gid >> 5, lane = gid & 31;
    float ss = 0.f, sd = 0.f;
    if (w < 512) {
        int k = w >> 2, h = w & 3;
        float4 wv = *(const float4*)&W1[(size_t)k * HC1 + h * C + lane * 4];
        float4 av = *(const float4*)&as1[h * C + lane * 4];
        float4 dv = *(const float4*)&ad1[h * C + lane * 4];
        ss = wv.x * av.x + wv.y * av.y + wv.z * av.z + wv.w * av.w;
        sd = wv.x * dv.x + wv.y * dv.y + wv.z * dv.z + wv.w * dv.w;
#pragma unroll
        for (int off = 16; off > 0; off >>= 1) {
            ss += __shfl_down_sync(0xffffffff, ss, off);
            sd += __shfl_down_sync(0xffffffff, sd, off);
        }
        if (lane == 0) { w_as1[k * H1 + h] = ss; w_ad1[k * H1 + h] = sd; }
    } else if (w < 640) {
        int k = w - 512;
        float4 wv = *(const float4*)&W2[(size_t)k * C + lane * 4];
        float4 av = *(const float4*)&as2[lane * 4];
        float4 dv = *(const float4*)&ad2[lane * 4];
        ss = wv.x * av.x + wv.y * av.y + wv.z * av.z + wv.w * av.w;
        sd = wv.x * dv.x + wv.y * dv.y + wv.z * dv.z + wv.w * dv.w;
#pragma unroll
        for (int off = 16; off > 0; off >>= 1) {
            ss += __shfl_down_sync(0xffffffff, ss, off);
            sd += __shfl_down_sync(0xffffffff, sd, off);
        }
        if (lane == 0) { w_as2[k] = ss; w_ad2[k] = sd; }
    }
}

// ================= CSR build =================
__global__ __launch_bounds__(256) void count_kernel(
    const int* __restrict__ ei, int* __restrict__ cnt)
{
    int i = blockIdx.x * blockDim.x + threadIdx.x;
    if (i >= E_TOT) return;
    int d = (i < N_EDGES) ? ei[N_EDGES + i] : (i - N_EDGES);
    atomicAdd(&cnt[d], 1);
}

__global__ __launch_bounds__(1024) void scan_kernel(
    const int* __restrict__ cnt, int* __restrict__ rowptr, int* __restrict__ cursor)
{
    __shared__ int part[1024];
    const int t = threadIdx.x;
    const int CHUNK = 20;
    int base = t * CHUNK;
    int s = 0;
#pragma unroll
    for (int k = 0; k < CHUNK; k++) {
        int i = base + k;
        if (i < N_NODES) s += cnt[i];
    }
    part[t] = s;
    __syncthreads();
    for (int off = 1; off < 1024; off <<= 1) {
        int v = (t >= off) ? part[t - off] : 0;
        __syncthreads();
        part[t] += v;
        __syncthreads();
    }
    int run = part[t] - s;
#pragma unroll
    for (int k = 0; k < CHUNK; k++) {
        int i = base + k;
        if (i < N_NODES) {
            rowptr[i] = run;
            cursor[i] = run;
            run += cnt[i];
        }
    }
    if (t == 1023) rowptr[N_NODES] = part[1023];
}

__global__ __launch_bounds__(256) void scatter_kernel(
    const int* __restrict__ ei, int* __restrict__ cursor, int* __restrict__ csrc)
{
    int i = blockIdx.x * blockDim.x + threadIdx.x;
    if (i >= E_TOT) return;
    int s, d;
    if (i < N_EDGES) { s = ei[i]; d = ei[N_EDGES + i]; }
    else { s = d = i - N_EDGES; }
    int pos = atomicAdd(&cursor[d], 1);
    csrc[pos] = s;
}

// ================= GEMM -> fp16 out; BM=BN=128, BK=16, 8x8 microtile, reg prefetch =================
__global__ __launch_bounds__(256) void sgemm_half_kernel(
    const float* __restrict__ A, const float* __restrict__ B,
    __half* __restrict__ Ch, int M, int N, int K)
{
    __shared__ float As[16][132];
    __shared__ float Bs[16][128];

    const int tid = threadIdx.x;
    const int tx = tid & 15;
    const int ty = tid >> 4;
    const int rowBase = blockIdx.y * 128;
    const int colBase = blockIdx.x * 128;

    const int a_row = tid >> 1;
    const int a_col = (tid & 1) * 8;
    const int b_row = tid >> 5;          // 0..7 (and +8)
    const int b_col = (tid & 31) * 4;

    float acc[8][8];
#pragma unroll
    for (int i = 0; i < 8; i++)
#pragma unroll
        for (int j = 0; j < 8; j++) acc[i][j] = 0.f;

    const int gr = rowBase + a_row;
    const bool arow_ok = (gr < M);

    float4 pa0 = make_float4(0.f,0.f,0.f,0.f), pa1 = pa0;
    if (arow_ok) {
        pa0 = *(const float4*)&A[(size_t)gr * K + a_col];
        pa1 = *(const float4*)&A[(size_t)gr * K + a_col + 4];
    }
    float4 pb0 = *(const float4*)&B[(size_t)b_row * N + colBase + b_col];
    float4 pb1 = *(const float4*)&B[(size_t)(b_row + 8) * N + colBase + b_col];

    As[a_col + 0][a_row] = pa0.x; As[a_col + 1][a_row] = pa0.y;
    As[a_col + 2][a_row] = pa0.z; As[a_col + 3][a_row] = pa0.w;
    As[a_col + 4][a_row] = pa1.x; As[a_col + 5][a_row] = pa1.y;
    As[a_col + 6][a_row] = pa1.z; As[a_col + 7][a_row] = pa1.w;
    *(float4*)&Bs[b_row][b_col]     = pb0;
    *(float4*)&Bs[b_row + 8][b_col] = pb1;
    __syncthreads();

    for (int k0 = 16; k0 < K; k0 += 16) {
        if (arow_ok) {
            pa0 = *(const float4*)&A[(size_t)gr * K + k0 + a_col];
            pa1 = *(const float4*)&A[(size_t)gr * K + k0 + a_col + 4];
        }
        pb0 = *(const float4*)&B[(size_t)(k0 + b_row) * N + colBase + b_col];
        pb1 = *(const float4*)&B[(size_t)(k0 + b_row + 8) * N + colBase + b_col];

#pragma unroll
        for (int kk = 0; kk < 16; kk++) {
            float a[8], b[8];
            *(float4*)&a[0] = *(const float4*)&As[kk][ty * 8];
            *(float4*)&a[4] = *(const float4*)&As[kk][ty * 8 + 4];
            *(float4*)&b[0] = *(const float4*)&Bs[kk][tx * 8];
            *(float4*)&b[4] = *(const float4*)&Bs[kk][tx * 8 + 4];
#pragma unroll
            for (int i = 0; i < 8; i++)
#pragma unroll
                for (int j = 0; j < 8; j++) acc[i][j] += a[i] * b[j];
        }
        __syncthreads();
        As[a_col + 0][a_row] = pa0.x; As[a_col + 1][a_row] = pa0.y;
        As[a_col + 2][a_row] = pa0.z; As[a_col + 3][a_row] = pa0.w;
        As[a_col + 4][a_row] = pa1.x; As[a_col + 5][a_row] = pa1.y;
        As[a_col + 6][a_row] = pa1.z; As[a_col + 7][a_row] = pa1.w;
        *(float4*)&Bs[b_row][b_col]     = pb0;
        *(float4*)&Bs[b_row + 8][b_col] = pb1;
        __syncthreads();
    }
#pragma unroll
    for (int kk = 0; kk < 16; kk++) {
        float a[8], b[8];
        *(float4*)&a[0] = *(const float4*)&As[kk][ty * 8];
        *(float4*)&a[4] = *(const float4*)&As[kk][ty * 8 + 4];
        *(float4*)&b[0] = *(const float4*)&Bs[kk][tx * 8];
        *(float4*)&b[4] = *(const float4*)&Bs[kk][tx * 8 + 4];
#pragma unroll
        for (int i = 0; i < 8; i++)
#pragma unroll
            for (int j = 0; j < 8; j++) acc[i][j] += a[i] * b[j];
    }

#pragma unroll
    for (int i = 0; i < 8; i++) {
        int r = rowBase + ty * 8 + i;
        if (r < M) {
            __half hb[8];
#pragma unroll
            for (int j = 0; j < 8; j++) hb[j] = __float2half(acc[i][j]);
            *(uint4*)&Ch[(size_t)r * N + colBase + tx * 8] = *(uint4*)hb;
        }
    }
}

// ================= layer-1 logits from x (folded weights) =================
__global__ __launch_bounds__(256) void alphas1_kernel(
    const float* __restrict__ x, const float* __restrict__ w_as1,
    const float* __restrict__ w_ad1, float* __restrict__ as_o,
    float* __restrict__ ad_o)
{
    __shared__ float sw_s[C * H1], sw_d[C * H1];
    for (int i = threadIdx.x; i < C * H1; i += 256) {
        sw_s[i] = w_as1[i]; sw_d[i] = w_ad1[i];
    }
    __syncthreads();
    int n = (blockIdx.x * 256 + threadIdx.x) >> 5;
    int lane = threadIdx.x & 31;
    if (n >= N_NODES) return;
    float4 xv = *(const float4*)&x[(size_t)n * C + lane * 4];
    float xs[4] = {xv.x, xv.y, xv.z, xv.w};
    float ps[4] = {0,0,0,0}, pd[4] = {0,0,0,0};
#pragma unroll
    for (int j = 0; j < 4; j++) {
        int k = lane * 4 + j;
#pragma unroll
        for (int h = 0; h < 4; h++) {
            ps[h] += xs[j] * sw_s[k * 4 + h];
            pd[h] += xs[j] * sw_d[k * 4 + h];
        }
    }
#pragma unroll
    for (int off = 16; off > 0; off >>= 1) {
#pragma unroll
        for (int h = 0; h < 4; h++) {
            ps[h] += __shfl_down_sync(0xffffffff, ps[h], off);
            pd[h] += __shfl_down_sync(0xffffffff, pd[h], off);
        }
    }
    if (lane == 0) {
        *(float4*)&as_o[n * 4] = make_float4(ps[0], ps[1], ps[2], ps[3]);
        *(float4*)&ad_o[n * 4] = make_float4(pd[0], pd[1], pd[2], pd[3]);
    }
}

// ================= layer-1 aggregation, all 4 heads/warp, fused finalize + layer-2 logits =================
__global__ __launch_bounds__(256) void agg1_kernel(
    const int* __restrict__ rowptr, const int* __restrict__ csrc,
    const float* __restrict__ as_v, const float* __restrict__ ad_v,
    const __half* __restrict__ h1h, const float* __restrict__ b1,
    const float* __restrict__ w_as2, const float* __restrict__ w_ad2,
    float* __restrict__ x2, float* __restrict__ as2_o, float* __restrict__ ad2_o)
{
    __shared__ float sw_s[C], sw_d[C];
    for (int i = threadIdx.x; i < C; i += 256) { sw_s[i] = w_as2[i]; sw_d[i] = w_ad2[i]; }
    __syncthreads();
    int n = (blockIdx.x * 256 + threadIdx.x) >> 5;
    int lane = threadIdx.x & 31;
    if (n >= N_NODES) return;
    int start = rowptr[n], end = rowptr[n + 1];
    float4 adn = *(const float4*)&ad_v[n * 4];

    float a0x=0,a0y=0,a0z=0,a0w=0, a1x=0,a1y=0,a1z=0,a1w=0;
    float a2x=0,a2y=0,a2z=0,a2w=0, a3x=0,a3y=0,a3z=0,a3w=0;
    float d0=0,d1=0,d2=0,d3=0;

    int sA = csrc[start];                       // deg >= 1 (self loop)
    float4 lgA = *(const float4*)&as_v[sA * 4];
    for (int e = start; e < end; e++) {
        int s = sA; float4 lg = lgA;
        if (e + 1 < end) {
            sA = csrc[e + 1];
            lgA = *(const float4*)&as_v[sA * 4];
        }
        float l0 = lg.x + adn.x; l0 = l0 > 0.f ? l0 : 0.2f * l0;
        float l1 = lg.y + adn.y; l1 = l1 > 0.f ? l1 : 0.2f * l1;
        float l2 = lg.z + adn.z; l2 = l2 > 0.f ? l2 : 0.2f * l2;
        float l3 = lg.w + adn.w; l3 = l3 > 0.f ? l3 : 0.2f * l3;
        float p0 = __expf(l0), p1 = __expf(l1), p2 = __expf(l2), p3 = __expf(l3);
        d0 += p0; d1 += p1; d2 += p2; d3 += p3;
        const __half2* row = (const __half2*)(h1h + (size_t)s * HC1);
        __half2 u00 = row[lane * 2],       u01 = row[lane * 2 + 1];
        __half2 u10 = row[64 + lane * 2],  u11 = row[64 + lane * 2 + 1];
        __half2 u20 = row[128 + lane * 2], u21 = row[128 + lane * 2 + 1];
        __half2 u30 = row[192 + lane * 2], u31 = row[192 + lane * 2 + 1];
        float2 f00 = __half22float2(u00), f01 = __half22float2(u01);
        float2 f10 = __half22float2(u10), f11 = __half22float2(u11);
        float2 f20 = __half22float2(u20), f21 = __half22float2(u21);
        float2 f30 = __half22float2(u30), f31 = __half22float2(u31);
        a0x += p0 * f00.x; a0y += p0 * f00.y; a0z += p0 * f01.x; a0w += p0 * f01.y;
        a1x += p1 * f10.x; a1y += p1 * f10.y; a1z += p1 * f11.x; a1w += p1 * f11.y;
        a2x += p2 * f20.x; a2y += p2 * f20.y; a2z += p2 * f21.x; a2w += p2 * f21.y;
        a3x += p3 * f30.x; a3y += p3 * f30.y; a3z += p3 * f31.x; a3w += p3 * f31.y;
    }
    float i0 = 1.f / d0, i1 = 1.f / d1, i2 = 1.f / d2, i3 = 1.f / d3;
    float4 bb = *(const float4*)&b1[lane * 4];
    float v0 = 0.25f * (a0x * i0 + a1x * i1 + a2x * i2 + a3x * i3) + bb.x;
    float v1 = 0.25f * (a0y * i0 + a1y * i1 + a2y * i2 + a3y * i3) + bb.y;
    float v2 = 0.25f * (a0z * i0 + a1z * i1 + a2z * i2 + a3z * i3) + bb.z;
    float v3 = 0.25f * (a0w * i0 + a1w * i1 + a2w * i2 + a3w * i3) + bb.w;
    v0 = v0 > 0.f ? v0 : expm1f(v0);
    v1 = v1 > 0.f ? v1 : expm1f(v1);
    v2 = v2 > 0.f ? v2 : expm1f(v2);
    v3 = v3 > 0.f ? v3 : expm1f(v3);
    *(float4*)&x2[(size_t)n * C + lane * 4] = make_float4(v0, v1, v2, v3);

    int k = lane * 4;
    float ps = v0 * sw_s[k] + v1 * sw_s[k+1] + v2 * sw_s[k+2] + v3 * sw_s[k+3];
    float pd = v0 * sw_d[k] + v1 * sw_d[k+1] + v2 * sw_d[k+2] + v3 * sw_d[k+3];
#pragma unroll
    for (int off = 16; off > 0; off >>= 1) {
        ps += __shfl_down_sync(0xffffffff, ps, off);
        pd += __shfl_down_sync(0xffffffff, pd, off);
    }
    if (lane == 0) { as2_o[n] = ps; ad2_o[n] = pd; }
}

// ================= layer-2 aggregation + finalize =================
__global__ __launch_bounds__(256) void agg2_kernel(
    const int* __restrict__ rowptr, const int* __restrict__ csrc,
    const float* __restrict__ as_v, const float* __restrict__ ad_v,
    const __half* __restrict__ h2h, const float* __restrict__ b2,
    float* __restrict__ out)
{
    int n = (blockIdx.x * 256 + threadIdx.x) >> 5;
    int lane = threadIdx.x & 31;
    if (n >= N_NODES) return;
    int start = rowptr[n], end = rowptr[n + 1];
    float adn = ad_v[n];

    float ax = 0.f, ay = 0.f, az = 0.f, aw = 0.f, den = 0.f;
    int sA = csrc[start];
    float lA = as_v[sA];
    for (int e = start; e < end; e++) {
        int s = sA; float l = lA;
        if (e + 1 < end) { sA = csrc[e + 1]; lA = as_v[sA]; }
        l += adn;
        l = l > 0.f ? l : 0.2f * l;
        float p = __expf(l);
        den += p;
        const __half2* row = (const __half2*)(h2h + (size_t)s * C);
        __half2 u0 = row[lane * 2], u1 = row[lane * 2 + 1];
        float2 f0 = __half22float2(u0), f1 = __half22float2(u1);
        ax += p * f0.x; ay += p * f0.y; az += p * f1.x; aw += p * f1.y;
    }
    float inv = 1.f / den;
    float4 bb = *(const float4*)&b2[lane * 4];
    float v0 = ax * inv + bb.x;
    float v1 = ay * inv + bb.y;
    float v2 = az * inv + bb.z;
    float v3 = aw * inv + bb.w;
    v0 = v0 > 0.f ? v0 : expm1f(v0);
    v1 = v1 > 0.f ? v1 : expm1f(v1);
    v2 = v2 > 0.f ? v2 : expm1f(v2);
    v3 = v3 > 0.f ? v3 : expm1f(v3);
    *(float4*)&out[(size_t)n * C + lane * 4] = make_float4(v0, v1, v2, v3);
}

// ---------------- launch ----------------
extern "C" void kernel_launch(void* const* d_in, const int* in_sizes, int n_in,
                              void* d_out, int out_size)
{
    const float* x      = (const float*)d_in[0];
    const float* W1     = (const float*)d_in[1];
    const float* a_src1 = (const float*)d_in[2];
    const float* a_dst1 = (const float*)d_in[3];
    const float* b1     = (const float*)d_in[4];
    const float* W2     = (const float*)d_in[5];
    const float* a_src2 = (const float*)d_in[6];
    const float* a_dst2 = (const float*)d_in[7];
    const float* b2     = (const float*)d_in[8];
    const int*   ei     = (const int*)d_in[9];
    float* out = (float*)d_out;

    __half *h1h, *h2h;
    float *as1, *ad1, *x2, *as2, *ad2, *was1, *wad1, *was2, *wad2;
    int *rowptr, *cursor, *cnt, *csrc;
    cudaGetSymbolAddress((void**)&h1h,    g_h1h);
    cudaGetSymbolAddress((void**)&h2h,    g_h2h);
    cudaGetSymbolAddress((void**)&as1,    g_as1);
    cudaGetSymbolAddress((void**)&ad1,    g_ad1);
    cudaGetSymbolAddress((void**)&x2,     g_x2);
    cudaGetSymbolAddress((void**)&as2,    g_as2);
    cudaGetSymbolAddress((void**)&ad2,    g_ad2);
    cudaGetSymbolAddress((void**)&was1,   g_was1);
    cudaGetSymbolAddress((void**)&wad1,   g_wad1);
    cudaGetSymbolAddress((void**)&was2,   g_was2);
    cudaGetSymbolAddress((void**)&wad2,   g_wad2);
    cudaGetSymbolAddress((void**)&rowptr, g_rowptr);
    cudaGetSymbolAddress((void**)&cursor, g_cursor);
    cudaGetSymbolAddress((void**)&cnt,    g_cnt);
    cudaGetSymbolAddress((void**)&csrc,   g_csrc);

    const int TPB = 256;

    // folded attention weights + cnt zeroing
    wfold_kernel<<<80, TPB>>>(W1, a_src1, a_dst1, W2, a_src2, a_dst2,
                              was1, wad1, was2, wad2, cnt);
    // CSR build
    count_kernel<<<(E_TOT + TPB - 1) / TPB, TPB>>>(ei, cnt);
    scan_kernel<<<1, 1024>>>(cnt, rowptr, cursor);
    scatter_kernel<<<(E_TOT + TPB - 1) / TPB, TPB>>>(ei, cursor, csrc);

    // layer 1
    dim3 g1(HC1 / 128, (N_NODES + 127) / 128);
    sgemm_half_kernel<<<g1, TPB>>>(x, W1, h1h, N_NODES, HC1, C);
    alphas1_kernel<<<(N_NODES * 32 + TPB - 1) / TPB, TPB>>>(x, was1, wad1, as1, ad1);
    agg1_kernel<<<(N_NODES * 32 + TPB - 1) / TPB, TPB>>>(
        rowptr, csrc, as1, ad1, h1h, b1, was2, wad2, x2, as2, ad2);

    // layer 2
    dim3 g2(C / 128, (N_NODES + 127) / 128);
    sgemm_half_kernel<<<g2, TPB>>>(x2, W2, h2h, N_NODES, C, C);
    agg2_kernel<<<(N_NODES * 32 + TPB - 1) / TPB, TPB>>>(
        rowptr, csrc, as2, ad2, h2h, b2, out);
}

// round 6
// speedup vs baseline: 2.4122x; 1.3381x over previous
#include <cuda_runtime.h>
#include <cuda_fp16.h>
#include <math.h>
#include <stdint.h>

#define N_NODES 20000
#define N_EDGES 640000
#define E_TOT   660000          // + self loops
#define H1      4
#define C       128
#define HC1     (H1 * C)        // 512

// ---------------- scratch (no allocations allowed) ----------------
__device__ __half g_xh[N_NODES * C];
__device__ __half g_W1h[C * HC1];
__device__ __half g_W2h[C * C];
__device__ __half g_h1h[N_NODES * HC1];
__device__ __half g_h2h[N_NODES * C];
__device__ __half g_x2h[N_NODES * C];
__device__ float  g_as1[N_NODES * H1];
__device__ float  g_ad1[N_NODES * H1];
__device__ float  g_as2[N_NODES];
__device__ float  g_ad2[N_NODES];
__device__ float  g_was1[C * H1];
__device__ float  g_wad1[C * H1];
__device__ float  g_was2[C];
__device__ float  g_wad2[C];
__device__ int    g_rowptr[N_NODES + 1];
__device__ int    g_cursor[N_NODES];
__device__ int    g_cnt[N_NODES];
__device__ int    g_csrc[E_TOT];

__device__ __forceinline__ unsigned int smem_u32(const void* p)
{
    return (unsigned int)__cvta_generic_to_shared(p);
}

// ================= fp32 -> fp16 conversion (x, W1, W2) =================
__global__ __launch_bounds__(256) void convert_kernel(
    const float* __restrict__ x, const float* __restrict__ W1,
    const float* __restrict__ W2, __half* __restrict__ xh,
    __half* __restrict__ W1h, __half* __restrict__ W2h)
{
    const int NX4 = N_NODES * C / 4;
    const int NW14 = C * HC1 / 4;
    const int NW24 = C * C / 4;
    int i = blockIdx.x * blockDim.x + threadIdx.x;
    if (i >= NX4 + NW14 + NW24) return;
    const float* src; __half* dst; int j;
    if (i < NX4) { src = x; dst = xh; j = i; }
    else if (i < NX4 + NW14) { src = W1; dst = W1h; j = i - NX4; }
    else { src = W2; dst = W2h; j = i - NX4 - NW14; }
    float4 v = ((const float4*)src)[j];
    __half2* d2 = (__half2*)(dst + (size_t)j * 4);
    d2[0] = __floats2half2_rn(v.x, v.y);
    d2[1] = __floats2half2_rn(v.z, v.w);
}

// ================= weight folding (+ cnt zero) =================
__global__ __launch_bounds__(256) void wfold_kernel(
    const float* __restrict__ W1, const float* __restrict__ as1,
    const float* __restrict__ ad1, const float* __restrict__ W2,
    const float* __restrict__ as2, const float* __restrict__ ad2,
    float* __restrict__ w_as1, float* __restrict__ w_ad1,
    float* __restrict__ w_as2, float* __restrict__ w_ad2,
    int* __restrict__ cnt)
{
    int gid = blockIdx.x * blockDim.x + threadIdx.x;
    if (gid < N_NODES) cnt[gid] = 0;
    int w = gid >> 5, lane = gid & 31;
    float ss = 0.f, sd = 0.f;
    if (w < 512) {
        int k = w >> 2, h = w & 3;
        float4 wv = *(const float4*)&W1[(size_t)k * HC1 + h * C + lane * 4];
        float4 av = *(const float4*)&as1[h * C + lane * 4];
        float4 dv = *(const float4*)&ad1[h * C + lane * 4];
        ss = wv.x * av.x + wv.y * av.y + wv.z * av.z + wv.w * av.w;
        sd = wv.x * dv.x + wv.y * dv.y + wv.z * dv.z + wv.w * dv.w;
#pragma unroll
        for (int off = 16; off > 0; off >>= 1) {
            ss += __shfl_down_sync(0xffffffff, ss, off);
            sd += __shfl_down_sync(0xffffffff, sd, off);
        }
        if (lane == 0) { w_as1[k * H1 + h] = ss; w_ad1[k * H1 + h] = sd; }
    } else if (w < 640) {
        int k = w - 512;
        float4 wv = *(const float4*)&W2[(size_t)k * C + lane * 4];
        float4 av = *(const float4*)&as2[lane * 4];
        float4 dv = *(const float4*)&ad2[lane * 4];
        ss = wv.x * av.x + wv.y * av.y + wv.z * av.z + wv.w * av.w;
        sd = wv.x * dv.x + wv.y * dv.y + wv.z * dv.z + wv.w * dv.w;
#pragma unroll
        for (int off = 16; off > 0; off >>= 1) {
            ss += __shfl_down_sync(0xffffffff, ss, off);
            sd += __shfl_down_sync(0xffffffff, sd, off);
        }
        if (lane == 0) { w_as2[k] = ss; w_ad2[k] = sd; }
    }
}

// ================= CSR build =================
__global__ __launch_bounds__(256) void count_kernel(
    const int* __restrict__ ei, int* __restrict__ cnt)
{
    int i = blockIdx.x * blockDim.x + threadIdx.x;
    if (i >= E_TOT) return;
    int d = (i < N_EDGES) ? ei[N_EDGES + i] : (i - N_EDGES);
    atomicAdd(&cnt[d], 1);
}

__global__ __launch_bounds__(1024) void scan_kernel(
    const int* __restrict__ cnt, int* __restrict__ rowptr, int* __restrict__ cursor)
{
    __shared__ int part[1024];
    const int t = threadIdx.x;
    const int CHUNK = 20;
    int base = t * CHUNK;
    int s = 0;
#pragma unroll
    for (int k = 0; k < CHUNK; k++) {
        int i = base + k;
        if (i < N_NODES) s += cnt[i];
    }
    part[t] = s;
    __syncthreads();
    for (int off = 1; off < 1024; off <<= 1) {
        int v = (t >= off) ? part[t - off] : 0;
        __syncthreads();
        part[t] += v;
        __syncthreads();
    }
    int run = part[t] - s;
#pragma unroll
    for (int k = 0; k < CHUNK; k++) {
        int i = base + k;
        if (i < N_NODES) {
            rowptr[i] = run;
            cursor[i] = run;
            run += cnt[i];
        }
    }
    if (t == 1023) rowptr[N_NODES] = part[1023];
}

__global__ __launch_bounds__(256) void scatter_kernel(
    const int* __restrict__ ei, int* __restrict__ cursor, int* __restrict__ csrc)
{
    int i = blockIdx.x * blockDim.x + threadIdx.x;
    if (i >= E_TOT) return;
    int s, d;
    if (i < N_EDGES) { s = ei[i]; d = ei[N_EDGES + i]; }
    else { s = d = i - N_EDGES; }
    int pos = atomicAdd(&cursor[d], 1);
    csrc[pos] = s;
}

// ================= tensor-core GEMM: C[M,N] = A[M,128]*B[128,N], fp16 in/out, fp32 acc =================
// CTA tile 128x64, K=128 fully resident, XOR-swizzled smem (48KB), 8 warps (4Mx2N), warp tile 32x32
__global__ __launch_bounds__(256) void hgemm_kernel(
    const __half* __restrict__ A, const __half* __restrict__ B,
    __half* __restrict__ Cmat, int M, int N)
{
    __shared__ __half As[128][128];
    __shared__ __half Bs[128][64];

    const int tid = threadIdx.x;
    const int lane = tid & 31, wid = tid >> 5;
    const int warpM = wid >> 1, warpN = wid & 1;
    const int rowBase = blockIdx.y * 128;
    const int colBase = blockIdx.x * 64;

    // load A tile (128 rows x 16 chunks of 8 halfs)
#pragma unroll
    for (int i = tid; i < 2048; i += 256) {
        int r = i >> 4, ch = i & 15;
        int gr = rowBase + r;
        uint4 v = make_uint4(0u, 0u, 0u, 0u);
        if (gr < M) v = *(const uint4*)&A[(size_t)gr * 128 + ch * 8];
        int sch = ch ^ (r & 7);
        *(uint4*)&As[r][sch * 8] = v;
    }
    // load B tile (128 rows x 8 chunks)
#pragma unroll
    for (int i = tid; i < 1024; i += 256) {
        int r = i >> 3, ch = i & 7;
        uint4 v = *(const uint4*)&B[(size_t)r * N + colBase + ch * 8];
        int sch = ch ^ (r & 7);
        *(uint4*)&Bs[r][sch * 8] = v;
    }
    __syncthreads();

    float acc[2][4][4];
#pragma unroll
    for (int mi = 0; mi < 2; mi++)
#pragma unroll
        for (int ni = 0; ni < 4; ni++)
#pragma unroll
            for (int q = 0; q < 4; q++) acc[mi][ni][q] = 0.f;

    const int arow0 = warpM * 32 + (lane & 15);
    const int brow0 = (lane & 15);
    const int hi = (lane >> 4);          // 0/1: second 8-chunk

#pragma unroll
    for (int kk = 0; kk < 8; kk++) {
        unsigned int a[2][4];
#pragma unroll
        for (int mi = 0; mi < 2; mi++) {
            int r = arow0 + mi * 16;
            int ch = (kk * 2 + hi) ^ (r & 7);
            unsigned int addr = smem_u32(&As[r][ch * 8]);
            asm volatile("ldmatrix.sync.aligned.m8n8.x4.shared.b16 {%0,%1,%2,%3}, [%4];"
                : "=r"(a[mi][0]), "=r"(a[mi][1]), "=r"(a[mi][2]), "=r"(a[mi][3])
                : "r"(addr));
        }
        unsigned int b[4][2];
#pragma unroll
        for (int np = 0; np < 2; np++) {
            int r = kk * 16 + brow0;
            int ch = (warpN * 4 + np * 2 + hi) ^ (r & 7);
            unsigned int addr = smem_u32(&Bs[r][ch * 8]);
            unsigned int r0, r1, r2, r3;
            asm volatile("ldmatrix.sync.aligned.m8n8.x4.trans.shared.b16 {%0,%1,%2,%3}, [%4];"
                : "=r"(r0), "=r"(r1), "=r"(r2), "=r"(r3) : "r"(addr));
            b[np * 2][0] = r0;     b[np * 2][1] = r1;
            b[np * 2 + 1][0] = r2; b[np * 2 + 1][1] = r3;
        }
#pragma unroll
        for (int mi = 0; mi < 2; mi++)
#pragma unroll
            for (int ni = 0; ni < 4; ni++)
                asm volatile(
                    "mma.sync.aligned.m16n8k16.row.col.f32.f16.f16.f32 "
                    "{%0,%1,%2,%3},{%4,%5,%6,%7},{%8,%9},{%0,%1,%2,%3};"
                    : "+f"(acc[mi][ni][0]), "+f"(acc[mi][ni][1]),
                      "+f"(acc[mi][ni][2]), "+f"(acc[mi][ni][3])
                    : "r"(a[mi][0]), "r"(a[mi][1]), "r"(a[mi][2]), "r"(a[mi][3]),
                      "r"(b[ni][0]), "r"(b[ni][1]));
    }

#pragma unroll
    for (int mi = 0; mi < 2; mi++) {
        int r0 = rowBase + warpM * 32 + mi * 16 + (lane >> 2);
#pragma unroll
        for (int ni = 0; ni < 4; ni++) {
            int cc = colBase + warpN * 32 + ni * 8 + (lane & 3) * 2;
            if (r0 < M)
                *(__half2*)&Cmat[(size_t)r0 * N + cc] =
                    __floats2half2_rn(acc[mi][ni][0], acc[mi][ni][1]);
            if (r0 + 8 < M)
                *(__half2*)&Cmat[(size_t)(r0 + 8) * N + cc] =
                    __floats2half2_rn(acc[mi][ni][2], acc[mi][ni][3]);
        }
    }
}

// ================= layer-1 logits from x (folded weights, fp32 exact) =================
__global__ __launch_bounds__(256) void alphas1_kernel(
    const float* __restrict__ x, const float* __restrict__ w_as1,
    const float* __restrict__ w_ad1, float* __restrict__ as_o,
    float* __restrict__ ad_o)
{
    __shared__ float sw_s[C * H1], sw_d[C * H1];
    for (int i = threadIdx.x; i < C * H1; i += 256) {
        sw_s[i] = w_as1[i]; sw_d[i] = w_ad1[i];
    }
    __syncthreads();
    int n = (blockIdx.x * 256 + threadIdx.x) >> 5;
    int lane = threadIdx.x & 31;
    if (n >= N_NODES) return;
    float4 xv = *(const float4*)&x[(size_t)n * C + lane * 4];
    float xs[4] = {xv.x, xv.y, xv.z, xv.w};
    float ps[4] = {0, 0, 0, 0}, pd[4] = {0, 0, 0, 0};
#pragma unroll
    for (int j = 0; j < 4; j++) {
        int k = lane * 4 + j;
#pragma unroll
        for (int h = 0; h < 4; h++) {
            ps[h] += xs[j] * sw_s[k * 4 + h];
            pd[h] += xs[j] * sw_d[k * 4 + h];
        }
    }
#pragma unroll
    for (int off = 16; off > 0; off >>= 1) {
#pragma unroll
        for (int h = 0; h < 4; h++) {
            ps[h] += __shfl_down_sync(0xffffffff, ps[h], off);
            pd[h] += __shfl_down_sync(0xffffffff, pd[h], off);
        }
    }
    if (lane == 0) {
        *(float4*)&as_o[n * 4] = make_float4(ps[0], ps[1], ps[2], ps[3]);
        *(float4*)&ad_o[n * 4] = make_float4(pd[0], pd[1], pd[2], pd[3]);
    }
}

// ================= layer-1 aggregation (4 heads/warp) + finalize + layer-2 logits =================
__global__ __launch_bounds__(256) void agg1_kernel(
    const int* __restrict__ rowptr, const int* __restrict__ csrc,
    const float* __restrict__ as_v, const float* __restrict__ ad_v,
    const __half* __restrict__ h1h, const float* __restrict__ b1,
    const float* __restrict__ w_as2, const float* __restrict__ w_ad2,
    __half* __restrict__ x2h, float* __restrict__ as2_o, float* __restrict__ ad2_o)
{
    __shared__ float sw_s[C], sw_d[C];
    for (int i = threadIdx.x; i < C; i += 256) { sw_s[i] = w_as2[i]; sw_d[i] = w_ad2[i]; }
    __syncthreads();
    int n = (blockIdx.x * 256 + threadIdx.x) >> 5;
    int lane = threadIdx.x & 31;
    if (n >= N_NODES) return;
    int start = rowptr[n], end = rowptr[n + 1];
    float4 adn = *(const float4*)&ad_v[n * 4];

    float a0x=0,a0y=0,a0z=0,a0w=0, a1x=0,a1y=0,a1z=0,a1w=0;
    float a2x=0,a2y=0,a2z=0,a2w=0, a3x=0,a3y=0,a3z=0,a3w=0;
    float d0=0,d1=0,d2=0,d3=0;

    int sA = csrc[start];                       // deg >= 1 (self loop)
    float4 lgA = *(const float4*)&as_v[sA * 4];
    for (int e = start; e < end; e++) {
        int s = sA; float4 lg = lgA;
        if (e + 1 < end) {
            sA = csrc[e + 1];
            lgA = *(const float4*)&as_v[sA * 4];
        }
        float l0 = lg.x + adn.x; l0 = l0 > 0.f ? l0 : 0.2f * l0;
        float l1 = lg.y + adn.y; l1 = l1 > 0.f ? l1 : 0.2f * l1;
        float l2 = lg.z + adn.z; l2 = l2 > 0.f ? l2 : 0.2f * l2;
        float l3 = lg.w + adn.w; l3 = l3 > 0.f ? l3 : 0.2f * l3;
        float p0 = __expf(l0), p1 = __expf(l1), p2 = __expf(l2), p3 = __expf(l3);
        d0 += p0; d1 += p1; d2 += p2; d3 += p3;
        const __half2* row = (const __half2*)(h1h + (size_t)s * HC1);
        __half2 u00 = row[lane * 2],       u01 = row[lane * 2 + 1];
        __half2 u10 = row[64 + lane * 2],  u11 = row[64 + lane * 2 + 1];
        __half2 u20 = row[128 + lane * 2], u21 = row[128 + lane * 2 + 1];
        __half2 u30 = row[192 + lane * 2], u31 = row[192 + lane * 2 + 1];
        float2 f00 = __half22float2(u00), f01 = __half22float2(u01);
        float2 f10 = __half22float2(u10), f11 = __half22float2(u11);
        float2 f20 = __half22float2(u20), f21 = __half22float2(u21);
        float2 f30 = __half22float2(u30), f31 = __half22float2(u31);
        a0x += p0 * f00.x; a0y += p0 * f00.y; a0z += p0 * f01.x; a0w += p0 * f01.y;
        a1x += p1 * f10.x; a1y += p1 * f10.y; a1z += p1 * f11.x; a1w += p1 * f11.y;
        a2x += p2 * f20.x; a2y += p2 * f20.y; a2z += p2 * f21.x; a2w += p2 * f21.y;
        a3x += p3 * f30.x; a3y += p3 * f30.y; a3z += p3 * f31.x; a3w += p3 * f31.y;
    }
    float i0 = 1.f / d0, i1 = 1.f / d1, i2 = 1.f / d2, i3 = 1.f / d3;
    float4 bb = *(const float4*)&b1[lane * 4];
    float v0 = 0.25f * (a0x * i0 + a1x * i1 + a2x * i2 + a3x * i3) + bb.x;
    float v1 = 0.25f * (a0y * i0 + a1y * i1 + a2y * i2 + a3y * i3) + bb.y;
    float v2 = 0.25f * (a0z * i0 + a1z * i1 + a2z * i2 + a3z * i3) + bb.z;
    float v3 = 0.25f * (a0w * i0 + a1w * i1 + a2w * i2 + a3w * i3) + bb.w;
    v0 = v0 > 0.f ? v0 : expm1f(v0);
    v1 = v1 > 0.f ? v1 : expm1f(v1);
    v2 = v2 > 0.f ? v2 : expm1f(v2);
    v3 = v3 > 0.f ? v3 : expm1f(v3);
    __half2* d2p = (__half2*)(x2h + (size_t)n * C + lane * 4);
    d2p[0] = __floats2half2_rn(v0, v1);
    d2p[1] = __floats2half2_rn(v2, v3);

    int k = lane * 4;
    float ps = v0 * sw_s[k] + v1 * sw_s[k+1] + v2 * sw_s[k+2] + v3 * sw_s[k+3];
    float pd = v0 * sw_d[k] + v1 * sw_d[k+1] + v2 * sw_d[k+2] + v3 * sw_d[k+3];
#pragma unroll
    for (int off = 16; off > 0; off >>= 1) {
        ps += __shfl_down_sync(0xffffffff, ps, off);
        pd += __shfl_down_sync(0xffffffff, pd, off);
    }
    if (lane == 0) { as2_o[n] = ps; ad2_o[n] = pd; }
}

// ================= layer-2 aggregation + finalize =================
__global__ __launch_bounds__(256) void agg2_kernel(
    const int* __restrict__ rowptr, const int* __restrict__ csrc,
    const float* __restrict__ as_v, const float* __restrict__ ad_v,
    const __half* __restrict__ h2h, const float* __restrict__ b2,
    float* __restrict__ out)
{
    int n = (blockIdx.x * 256 + threadIdx.x) >> 5;
    int lane = threadIdx.x & 31;
    if (n >= N_NODES) return;
    int start = rowptr[n], end = rowptr[n + 1];
    float adn = ad_v[n];

    float ax = 0.f, ay = 0.f, az = 0.f, aw = 0.f, den = 0.f;
    int sA = csrc[start];
    float lA = as_v[sA];
    for (int e = start; e < end; e++) {
        int s = sA; float l = lA;
        if (e + 1 < end) { sA = csrc[e + 1]; lA = as_v[sA]; }
        l += adn;
        l = l > 0.f ? l : 0.2f * l;
        float p = __expf(l);
        den += p;
        const __half2* row = (const __half2*)(h2h + (size_t)s * C);
        __half2 u0 = row[lane * 2], u1 = row[lane * 2 + 1];
        float2 f0 = __half22float2(u0), f1 = __half22float2(u1);
        ax += p * f0.x; ay += p * f0.y; az += p * f1.x; aw += p * f1.y;
    }
    float inv = 1.f / den;
    float4 bb = *(const float4*)&b2[lane * 4];
    float v0 = ax * inv + bb.x;
    float v1 = ay * inv + bb.y;
    float v2 = az * inv + bb.z;
    float v3 = aw * inv + bb.w;
    v0 = v0 > 0.f ? v0 : expm1f(v0);
    v1 = v1 > 0.f ? v1 : expm1f(v1);
    v2 = v2 > 0.f ? v2 : expm1f(v2);
    v3 = v3 > 0.f ? v3 : expm1f(v3);
    *(float4*)&out[(size_t)n * C + lane * 4] = make_float4(v0, v1, v2, v3);
}

// ---------------- launch ----------------
extern "C" void kernel_launch(void* const* d_in, const int* in_sizes, int n_in,
                              void* d_out, int out_size)
{
    const float* x      = (const float*)d_in[0];
    const float* W1     = (const float*)d_in[1];
    const float* a_src1 = (const float*)d_in[2];
    const float* a_dst1 = (const float*)d_in[3];
    const float* b1     = (const float*)d_in[4];
    const float* W2     = (const float*)d_in[5];
    const float* a_src2 = (const float*)d_in[6];
    const float* a_dst2 = (const float*)d_in[7];
    const float* b2     = (const float*)d_in[8];
    const int*   ei     = (const int*)d_in[9];
    float* out = (float*)d_out;

    __half *xh, *W1h, *W2h, *h1h, *h2h, *x2h;
    float *as1, *ad1, *as2, *ad2, *was1, *wad1, *was2, *wad2;
    int *rowptr, *cursor, *cnt, *csrc;
    cudaGetSymbolAddress((void**)&xh,     g_xh);
    cudaGetSymbolAddress((void**)&W1h,    g_W1h);
    cudaGetSymbolAddress((void**)&W2h,    g_W2h);
    cudaGetSymbolAddress((void**)&h1h,    g_h1h);
    cudaGetSymbolAddress((void**)&h2h,    g_h2h);
    cudaGetSymbolAddress((void**)&x2h,    g_x2h);
    cudaGetSymbolAddress((void**)&as1,    g_as1);
    cudaGetSymbolAddress((void**)&ad1,    g_ad1);
    cudaGetSymbolAddress((void**)&as2,    g_as2);
    cudaGetSymbolAddress((void**)&ad2,    g_ad2);
    cudaGetSymbolAddress((void**)&was1,   g_was1);
    cudaGetSymbolAddress((void**)&wad1,   g_wad1);
    cudaGetSymbolAddress((void**)&was2,   g_was2);
    cudaGetSymbolAddress((void**)&wad2,   g_wad2);
    cudaGetSymbolAddress((void**)&rowptr, g_rowptr);
    cudaGetSymbolAddress((void**)&cursor, g_cursor);
    cudaGetSymbolAddress((void**)&cnt,    g_cnt);
    cudaGetSymbolAddress((void**)&csrc,   g_csrc);

    const int TPB = 256;

    // folded attention weights + cnt zeroing; fp16 conversions
    wfold_kernel<<<80, TPB>>>(W1, a_src1, a_dst1, W2, a_src2, a_dst2,
                              was1, wad1, was2, wad2, cnt);
    int conv_total = (N_NODES * C + C * HC1 + C * C) / 4;
    convert_kernel<<<(conv_total + TPB - 1) / TPB, TPB>>>(x, W1, W2, xh, W1h, W2h);

    // CSR build
    count_kernel<<<(E_TOT + TPB - 1) / TPB, TPB>>>(ei, cnt);
    scan_kernel<<<1, 1024>>>(cnt, rowptr, cursor);
    scatter_kernel<<<(E_TOT + TPB - 1) / TPB, TPB>>>(ei, cursor, csrc);

    // layer 1
    dim3 g1(HC1 / 64, (N_NODES + 127) / 128);
    hgemm_kernel<<<g1, TPB>>>(xh, W1h, h1h, N_NODES, HC1);
    alphas1_kernel<<<(N_NODES * 32 + TPB - 1) / TPB, TPB>>>(x, was1, wad1, as1, ad1);
    agg1_kernel<<<(N_NODES * 32 + TPB - 1) / TPB, TPB>>>(
        rowptr, csrc, as1, ad1, h1h, b1, was2, wad2, x2h, as2, ad2);

    // layer 2
    dim3 g2(C / 64, (N_NODES + 127) / 128);
    hgemm_kernel<<<g2, TPB>>>(x2h, W2h, h2h, N_NODES, C);
    agg2_kernel<<<(N_NODES * 32 + TPB - 1) / TPB, TPB>>>(
        rowptr, csrc, as2, ad2, h2h, b2, out);
}

// round 7
// speedup vs baseline: 2.9350x; 1.2167x over previous
#include <cuda_runtime.h>
#include <cuda_fp16.h>
#include <math.h>
#include <stdint.h>

#define N_NODES 20000
#define N_EDGES 640000
#define E_TOT   660000          // + self loops
#define H1      4
#define C       128
#define HC1     (H1 * C)        // 512

// ---------------- scratch (no allocations allowed) ----------------
__device__ __half g_xh[N_NODES * C];
__device__ __half g_W1h[C * HC1];
__device__ __half g_W2h[C * C];
__device__ __half g_h1h[N_NODES * HC1];
__device__ __half g_h2h[N_NODES * C];
__device__ __half g_x2h[N_NODES * C];
__device__ float  g_as1[N_NODES * H1];
__device__ float  g_ad1[N_NODES * H1];
__device__ float  g_as2[N_NODES];
__device__ float  g_ad2[N_NODES];
__device__ float  g_was1[C * H1];
__device__ float  g_wad1[C * H1];
__device__ float  g_was2[C];
__device__ float  g_wad2[C];
__device__ int    g_rowptr[N_NODES + 1];
__device__ int    g_cursor[N_NODES];
__device__ int    g_cnt[N_NODES];       // zero-initialized; scan re-zeroes after use
__device__ int    g_csrc[E_TOT];

__device__ __forceinline__ unsigned int smem_u32(const void* p)
{
    return (unsigned int)__cvta_generic_to_shared(p);
}

// ================= prep: wfold + fp16 convert + degree count, one kernel =================
__global__ __launch_bounds__(256) void prep_kernel(
    const float* __restrict__ x,  const float* __restrict__ W1,
    const float* __restrict__ W2, const float* __restrict__ as1,
    const float* __restrict__ ad1, const float* __restrict__ as2,
    const float* __restrict__ ad2, const int* __restrict__ ei,
    __half* __restrict__ xh, __half* __restrict__ W1h, __half* __restrict__ W2h,
    float* __restrict__ w_as1, float* __restrict__ w_ad1,
    float* __restrict__ w_as2, float* __restrict__ w_ad2,
    int* __restrict__ cnt)
{
    const int NX4  = N_NODES * C / 4;
    const int NW14 = C * HC1 / 4;
    const int NW24 = C * C / 4;
    const int CONV_TOTAL = NX4 + NW14 + NW24;
    int gid = blockIdx.x * blockDim.x + threadIdx.x;

    // --- fp32->fp16 convert ---
    if (gid < CONV_TOTAL) {
        const float* src; __half* dst; int j;
        if (gid < NX4) { src = x; dst = xh; j = gid; }
        else if (gid < NX4 + NW14) { src = W1; dst = W1h; j = gid - NX4; }
        else { src = W2; dst = W2h; j = gid - NX4 - NW14; }
        float4 v = ((const float4*)src)[j];
        __half2* d2 = (__half2*)(dst + (size_t)j * 4);
        d2[0] = __floats2half2_rn(v.x, v.y);
        d2[1] = __floats2half2_rn(v.z, v.w);
    }
    // --- degree count ---
    if (gid < E_TOT) {
        int d = (gid < N_EDGES) ? ei[N_EDGES + gid] : (gid - N_EDGES);
        atomicAdd(&cnt[d], 1);
    }
    // --- weight folding (first 640 warps) ---
    int w = gid >> 5, lane = gid & 31;
    if (w < 512) {
        int k = w >> 2, h = w & 3;
        float4 wv = *(const float4*)&W1[(size_t)k * HC1 + h * C + lane * 4];
        float4 av = *(const float4*)&as1[h * C + lane * 4];
        float4 dv = *(const float4*)&ad1[h * C + lane * 4];
        float ss = wv.x * av.x + wv.y * av.y + wv.z * av.z + wv.w * av.w;
        float sd = wv.x * dv.x + wv.y * dv.y + wv.z * dv.z + wv.w * dv.w;
#pragma unroll
        for (int off = 16; off > 0; off >>= 1) {
            ss += __shfl_down_sync(0xffffffff, ss, off);
            sd += __shfl_down_sync(0xffffffff, sd, off);
        }
        if (lane == 0) { w_as1[k * H1 + h] = ss; w_ad1[k * H1 + h] = sd; }
    } else if (w < 640) {
        int k = w - 512;
        float4 wv = *(const float4*)&W2[(size_t)k * C + lane * 4];
        float4 av = *(const float4*)&as2[lane * 4];
        float4 dv = *(const float4*)&ad2[lane * 4];
        float ss = wv.x * av.x + wv.y * av.y + wv.z * av.z + wv.w * av.w;
        float sd = wv.x * dv.x + wv.y * dv.y + wv.z * dv.z + wv.w * dv.w;
#pragma unroll
        for (int off = 16; off > 0; off >>= 1) {
            ss += __shfl_down_sync(0xffffffff, ss, off);
            sd += __shfl_down_sync(0xffffffff, sd, off);
        }
        if (lane == 0) { w_as2[k] = ss; w_ad2[k] = sd; }
    }
}

// ================= coalesced smem-staged scan (1 block); zeroes cnt afterward =================
#define SCAN_ELEMS 20480   // 1024 * 20
__global__ __launch_bounds__(1024) void scan_kernel(
    int* __restrict__ cnt, int* __restrict__ rowptr, int* __restrict__ cursor)
{
    extern __shared__ int sm[];           // SCAN_ELEMS ints = 80KB
    __shared__ int part[1024];
    const int t = threadIdx.x;
    const int CHUNK = 20;

    for (int i = t; i < SCAN_ELEMS; i += 1024)
        sm[i] = (i < N_NODES) ? cnt[i] : 0;
    __syncthreads();

    int base = t * CHUNK;
    int s = 0;
#pragma unroll
    for (int k = 0; k < CHUNK; k++) s += sm[base + k];
    part[t] = s;
    __syncthreads();
    for (int off = 1; off < 1024; off <<= 1) {
        int v = (t >= off) ? part[t - off] : 0;
        __syncthreads();
        part[t] += v;
        __syncthreads();
    }
    int run = part[t] - s;   // exclusive prefix of this thread's chunk
#pragma unroll
    for (int k = 0; k < CHUNK; k++) {
        int c = sm[base + k];
        sm[base + k] = run;   // replace with exclusive prefix
        run += c;
    }
    __syncthreads();
    for (int i = t; i < N_NODES; i += 1024) {
        int v = sm[i];
        rowptr[i] = v;
        cursor[i] = v;
        cnt[i] = 0;           // restore for next call
    }
    if (t == 1023) rowptr[N_NODES] = part[1023];
}

// ================= tensor-core GEMM body: C[M,N]=A[M,128]*B[128,N]; CTA 128x64, BK=64, 24KB smem =================
__device__ __forceinline__ void gemm_body(
    const __half* __restrict__ A, const __half* __restrict__ B,
    __half* __restrict__ Cmat, int M, int N, int bx, int by)
{
    __shared__ __half As[128][64];
    __shared__ __half Bs[64][64];

    const int tid = threadIdx.x;
    const int lane = tid & 31, wid = tid >> 5;
    const int warpM = wid >> 1, warpN = wid & 1;
    const int rowBase = by * 128;
    const int colBase = bx * 64;

    float acc[2][4][4];
#pragma unroll
    for (int mi = 0; mi < 2; mi++)
#pragma unroll
        for (int ni = 0; ni < 4; ni++)
#pragma unroll
            for (int q = 0; q < 4; q++) acc[mi][ni][q] = 0.f;

    const int arow0 = warpM * 32 + (lane & 15);
    const int brow0 = (lane & 15);
    const int hi = (lane >> 4);

#pragma unroll
    for (int kt = 0; kt < 2; kt++) {
        // A tile: 128 rows x 8 chunks of 8 halfs
#pragma unroll
        for (int i = tid; i < 1024; i += 256) {
            int r = i >> 3, ch = i & 7;
            int gr = rowBase + r;
            uint4 v = make_uint4(0u, 0u, 0u, 0u);
            if (gr < M) v = *(const uint4*)&A[(size_t)gr * 128 + kt * 64 + ch * 8];
            int sch = ch ^ (r & 7);
            *(uint4*)&As[r][sch * 8] = v;
        }
        // B tile: 64 rows x 8 chunks
#pragma unroll
        for (int i = tid; i < 512; i += 256) {
            int r = i >> 3, ch = i & 7;
            uint4 v = *(const uint4*)&B[(size_t)(kt * 64 + r) * N + colBase + ch * 8];
            int sch = ch ^ (r & 7);
            *(uint4*)&Bs[r][sch * 8] = v;
        }
        __syncthreads();

#pragma unroll
        for (int kk = 0; kk < 4; kk++) {
            unsigned int a[2][4];
#pragma unroll
            for (int mi = 0; mi < 2; mi++) {
                int r = arow0 + mi * 16;
                int ch = (kk * 2 + hi) ^ (r & 7);
                unsigned int addr = smem_u32(&As[r][ch * 8]);
                asm volatile("ldmatrix.sync.aligned.m8n8.x4.shared.b16 {%0,%1,%2,%3}, [%4];"
                    : "=r"(a[mi][0]), "=r"(a[mi][1]), "=r"(a[mi][2]), "=r"(a[mi][3])
                    : "r"(addr));
            }
            unsigned int b[4][2];
#pragma unroll
            for (int np = 0; np < 2; np++) {
                int r = kk * 16 + brow0;
                int ch = (warpN * 4 + np * 2 + hi) ^ (r & 7);
                unsigned int addr = smem_u32(&Bs[r][ch * 8]);
                unsigned int r0, r1, r2, r3;
                asm volatile("ldmatrix.sync.aligned.m8n8.x4.trans.shared.b16 {%0,%1,%2,%3}, [%4];"
                    : "=r"(r0), "=r"(r1), "=r"(r2), "=r"(r3) : "r"(addr));
                b[np * 2][0] = r0;     b[np * 2][1] = r1;
                b[np * 2 + 1][0] = r2; b[np * 2 + 1][1] = r3;
            }
#pragma unroll
            for (int mi = 0; mi < 2; mi++)
#pragma unroll
                for (int ni = 0; ni < 4; ni++)
                    asm volatile(
                        "mma.sync.aligned.m16n8k16.row.col.f32.f16.f16.f32 "
                        "{%0,%1,%2,%3},{%4,%5,%6,%7},{%8,%9},{%0,%1,%2,%3};"
                        : "+f"(acc[mi][ni][0]), "+f"(acc[mi][ni][1]),
                          "+f"(acc[mi][ni][2]), "+f"(acc[mi][ni][3])
                        : "r"(a[mi][0]), "r"(a[mi][1]), "r"(a[mi][2]), "r"(a[mi][3]),
                          "r"(b[ni][0]), "r"(b[ni][1]));
        }
        __syncthreads();
    }

#pragma unroll
    for (int mi = 0; mi < 2; mi++) {
        int r0 = rowBase + warpM * 32 + mi * 16 + (lane >> 2);
#pragma unroll
        for (int ni = 0; ni < 4; ni++) {
            int cc = colBase + warpN * 32 + ni * 8 + (lane & 3) * 2;
            if (r0 < M)
                *(__half2*)&Cmat[(size_t)r0 * N + cc] =
                    __floats2half2_rn(acc[mi][ni][0], acc[mi][ni][1]);
            if (r0 + 8 < M)
                *(__half2*)&Cmat[(size_t)(r0 + 8) * N + cc] =
                    __floats2half2_rn(acc[mi][ni][2], acc[mi][ni][3]);
        }
    }
}

// ================= fused: gemm1 + CSR scatter + layer-1 logits =================
#define G1_BLOCKS  (8 * 157)          // 512/64 cols x ceil(20000/128) rows
#define SC_BLOCKS  ((E_TOT + 255) / 256)
#define AL_BLOCKS  ((N_NODES * 32 + 255) / 256)
__global__ __launch_bounds__(256) void fused3_kernel(
    const __half* __restrict__ xh, const __half* __restrict__ W1h,
    __half* __restrict__ h1h,
    const int* __restrict__ ei, int* __restrict__ cursor, int* __restrict__ csrc,
    const float* __restrict__ x, const float* __restrict__ w_as1,
    const float* __restrict__ w_ad1, float* __restrict__ as_o,
    float* __restrict__ ad_o)
{
    int bid = blockIdx.x;
    if (bid < G1_BLOCKS) {
        gemm_body(xh, W1h, h1h, N_NODES, HC1, bid & 7, bid >> 3);
        return;
    }
    bid -= G1_BLOCKS;
    if (bid < SC_BLOCKS) {
        int i = bid * 256 + threadIdx.x;
        if (i < E_TOT) {
            int s, d;
            if (i < N_EDGES) { s = ei[i]; d = ei[N_EDGES + i]; }
            else { s = d = i - N_EDGES; }
            int pos = atomicAdd(&cursor[d], 1);
            csrc[pos] = s;
        }
        return;
    }
    bid -= SC_BLOCKS;
    {
        __shared__ float sw_s[C * H1], sw_d[C * H1];
        for (int i = threadIdx.x; i < C * H1; i += 256) {
            sw_s[i] = w_as1[i]; sw_d[i] = w_ad1[i];
        }
        __syncthreads();
        int n = (bid * 256 + threadIdx.x) >> 5;
        int lane = threadIdx.x & 31;
        if (n >= N_NODES) return;
        float4 xv = *(const float4*)&x[(size_t)n * C + lane * 4];
        float xs[4] = {xv.x, xv.y, xv.z, xv.w};
        float ps[4] = {0, 0, 0, 0}, pd[4] = {0, 0, 0, 0};
#pragma unroll
        for (int j = 0; j < 4; j++) {
            int k = lane * 4 + j;
#pragma unroll
            for (int h = 0; h < 4; h++) {
                ps[h] += xs[j] * sw_s[k * 4 + h];
                pd[h] += xs[j] * sw_d[k * 4 + h];
            }
        }
#pragma unroll
        for (int off = 16; off > 0; off >>= 1) {
#pragma unroll
            for (int h = 0; h < 4; h++) {
                ps[h] += __shfl_down_sync(0xffffffff, ps[h], off);
                pd[h] += __shfl_down_sync(0xffffffff, pd[h], off);
            }
        }
        if (lane == 0) {
            *(float4*)&as_o[n * 4] = make_float4(ps[0], ps[1], ps[2], ps[3]);
            *(float4*)&ad_o[n * 4] = make_float4(pd[0], pd[1], pd[2], pd[3]);
        }
    }
}

// ================= standalone GEMM kernel (layer 2) =================
__global__ __launch_bounds__(256) void hgemm_kernel(
    const __half* __restrict__ A, const __half* __restrict__ B,
    __half* __restrict__ Cmat, int M, int N)
{
    gemm_body(A, B, Cmat, M, N, blockIdx.x, blockIdx.y);
}

// ================= layer-1 aggregation: lane-split heads, fused finalize + layer-2 logits =================
__global__ __launch_bounds__(256) void agg1_kernel(
    const int* __restrict__ rowptr, const int* __restrict__ csrc,
    const float* __restrict__ as_v, const float* __restrict__ ad_v,
    const __half* __restrict__ h1h, const float* __restrict__ b1,
    const float* __restrict__ w_as2, const float* __restrict__ w_ad2,
    __half* __restrict__ x2h, float* __restrict__ as2_o, float* __restrict__ ad2_o)
{
    __shared__ float sw_s[C], sw_d[C];
    for (int i = threadIdx.x; i < C; i += 256) { sw_s[i] = w_as2[i]; sw_d[i] = w_ad2[i]; }
    __syncthreads();
    int n = (blockIdx.x * 256 + threadIdx.x) >> 5;
    int lane = threadIdx.x & 31;
    if (n >= N_NODES) return;
    int start = rowptr[n], end = rowptr[n + 1];
    float4 adn = *(const float4*)&ad_v[n * 4];
    const int grp = lane >> 4;           // 0: heads 0/2, 1: heads 1/3

    float accA[8], accB[8];
#pragma unroll
    for (int j = 0; j < 8; j++) { accA[j] = 0.f; accB[j] = 0.f; }
    float d0 = 0.f, d1 = 0.f, d2 = 0.f, d3 = 0.f;

    int sA = csrc[start];                // deg >= 1 (self loop)
    float4 lgA = *(const float4*)&as_v[sA * 4];
    for (int e = start; e < end; e++) {
        int s = sA; float4 lg = lgA;
        if (e + 1 < end) {
            sA = csrc[e + 1];
            lgA = *(const float4*)&as_v[sA * 4];
        }
        float l0 = lg.x + adn.x; l0 = l0 > 0.f ? l0 : 0.2f * l0;
        float l1 = lg.y + adn.y; l1 = l1 > 0.f ? l1 : 0.2f * l1;
        float l2 = lg.z + adn.z; l2 = l2 > 0.f ? l2 : 0.2f * l2;
        float l3 = lg.w + adn.w; l3 = l3 > 0.f ? l3 : 0.2f * l3;
        float p0 = __expf(l0), p1 = __expf(l1), p2 = __expf(l2), p3 = __expf(l3);
        d0 += p0; d1 += p1; d2 += p2; d3 += p3;
        const uint4* row = (const uint4*)(h1h + (size_t)s * HC1);
        uint4 qa = row[lane];            // heads 0/1, 8 halfs for this lane's channels
        uint4 qb = row[32 + lane];       // heads 2/3
        float pa = grp ? p1 : p0;
        float pb = grp ? p3 : p2;
        const __half2* ha = (const __half2*)&qa;
        const __half2* hb = (const __half2*)&qb;
#pragma unroll
        for (int j = 0; j < 4; j++) {
            float2 fa = __half22float2(ha[j]);
            float2 fb = __half22float2(hb[j]);
            accA[2*j]   += pa * fa.x; accA[2*j+1] += pa * fa.y;
            accB[2*j]   += pb * fb.x; accB[2*j+1] += pb * fb.y;
        }
    }
    float invA = 1.f / (grp ? d1 : d0);
    float invB = 1.f / (grp ? d3 : d2);
    const int sub = lane & 15;
    float4 bb0 = *(const float4*)&b1[sub * 8];
    float4 bb1 = *(const float4*)&b1[sub * 8 + 4];
    float bbar[8] = {bb0.x, bb0.y, bb0.z, bb0.w, bb1.x, bb1.y, bb1.z, bb1.w};

    float v[8];
    __half hout[8];
#pragma unroll
    for (int j = 0; j < 8; j++) {
        float vA = accA[j] * invA;
        float vB = accB[j] * invB;
        vA += __shfl_xor_sync(0xffffffff, vA, 16);   // head0+head1
        vB += __shfl_xor_sync(0xffffffff, vB, 16);   // head2+head3
        float val = 0.25f * (vA + vB) + bbar[j];
        val = val > 0.f ? val : expm1f(val);
        v[j] = val;
        hout[j] = __float2half(val);
    }
    if (lane < 16)
        *(uint4*)&x2h[(size_t)n * C + sub * 8] = *(uint4*)hout;

    float ps = 0.f, pd = 0.f;
#pragma unroll
    for (int j = 0; j < 8; j++) {
        ps += v[j] * sw_s[sub * 8 + j];
        pd += v[j] * sw_d[sub * 8 + j];
    }
#pragma unroll
    for (int off = 16; off > 0; off >>= 1) {
        ps += __shfl_down_sync(0xffffffff, ps, off);
        pd += __shfl_down_sync(0xffffffff, pd, off);
    }
    if (lane == 0) { as2_o[n] = 0.5f * ps; ad2_o[n] = 0.5f * pd; }   // halves double-count
}

// ================= layer-2 aggregation + finalize =================
__global__ __launch_bounds__(256) void agg2_kernel(
    const int* __restrict__ rowptr, const int* __restrict__ csrc,
    const float* __restrict__ as_v, const float* __restrict__ ad_v,
    const __half* __restrict__ h2h, const float* __restrict__ b2,
    float* __restrict__ out)
{
    int n = (blockIdx.x * 256 + threadIdx.x) >> 5;
    int lane = threadIdx.x & 31;
    if (n >= N_NODES) return;
    int start = rowptr[n], end = rowptr[n + 1];
    float adn = ad_v[n];

    float ax = 0.f, ay = 0.f, az = 0.f, aw = 0.f, den = 0.f;
    int sA = csrc[start];
    float lA = as_v[sA];
    for (int e = start; e < end; e++) {
        int s = sA; float l = lA;
        if (e + 1 < end) { sA = csrc[e + 1]; lA = as_v[sA]; }
        l += adn;
        l = l > 0.f ? l : 0.2f * l;
        float p = __expf(l);
        den += p;
        uint2 q = *(const uint2*)(h2h + (size_t)s * C + lane * 4);
        const __half2* h = (const __half2*)&q;
        float2 f0 = __half22float2(h[0]), f1 = __half22float2(h[1]);
        ax += p * f0.x; ay += p * f0.y; az += p * f1.x; aw += p * f1.y;
    }
    float inv = 1.f / den;
    float4 bb = *(const float4*)&b2[lane * 4];
    float v0 = ax * inv + bb.x;
    float v1 = ay * inv + bb.y;
    float v2 = az * inv + bb.z;
    float v3 = aw * inv + bb.w;
    v0 = v0 > 0.f ? v0 : expm1f(v0);
    v1 = v1 > 0.f ? v1 : expm1f(v1);
    v2 = v2 > 0.f ? v2 : expm1f(v2);
    v3 = v3 > 0.f ? v3 : expm1f(v3);
    *(float4*)&out[(size_t)n * C + lane * 4] = make_float4(v0, v1, v2, v3);
}

// ---------------- launch ----------------
extern "C" void kernel_launch(void* const* d_in, const int* in_sizes, int n_in,
                              void* d_out, int out_size)
{
    const float* x      = (const float*)d_in[0];
    const float* W1     = (const float*)d_in[1];
    const float* a_src1 = (const float*)d_in[2];
    const float* a_dst1 = (const float*)d_in[3];
    const float* b1     = (const float*)d_in[4];
    const float* W2     = (const float*)d_in[5];
    const float* a_src2 = (const float*)d_in[6];
    const float* a_dst2 = (const float*)d_in[7];
    const float* b2     = (const float*)d_in[8];
    const int*   ei     = (const int*)d_in[9];
    float* out = (float*)d_out;

    __half *xh, *W1h, *W2h, *h1h, *h2h, *x2h;
    float *as1, *ad1, *as2, *ad2, *was1, *wad1, *was2, *wad2;
    int *rowptr, *cursor, *cnt, *csrc;
    cudaGetSymbolAddress((void**)&xh,     g_xh);
    cudaGetSymbolAddress((void**)&W1h,    g_W1h);
    cudaGetSymbolAddress((void**)&W2h,    g_W2h);
    cudaGetSymbolAddress((void**)&h1h,    g_h1h);
    cudaGetSymbolAddress((void**)&h2h,    g_h2h);
    cudaGetSymbolAddress((void**)&x2h,    g_x2h);
    cudaGetSymbolAddress((void**)&as1,    g_as1);
    cudaGetSymbolAddress((void**)&ad1,    g_ad1);
    cudaGetSymbolAddress((void**)&as2,    g_as2);
    cudaGetSymbolAddress((void**)&ad2,    g_ad2);
    cudaGetSymbolAddress((void**)&was1,   g_was1);
    cudaGetSymbolAddress((void**)&wad1,   g_wad1);
    cudaGetSymbolAddress((void**)&was2,   g_was2);
    cudaGetSymbolAddress((void**)&wad2,   g_wad2);
    cudaGetSymbolAddress((void**)&rowptr, g_rowptr);
    cudaGetSymbolAddress((void**)&cursor, g_cursor);
    cudaGetSymbolAddress((void**)&cnt,    g_cnt);
    cudaGetSymbolAddress((void**)&csrc,   g_csrc);

    const int TPB = 256;
    const int CONV_TOTAL = (N_NODES * C + C * HC1 + C * C) / 4;
    int prep_blocks = (CONV_TOTAL + TPB - 1) / TPB;           // covers E_TOT too
    if (prep_blocks < (E_TOT + TPB - 1) / TPB) prep_blocks = (E_TOT + TPB - 1) / TPB;

    cudaFuncSetAttribute(scan_kernel, cudaFuncAttributeMaxDynamicSharedMemorySize,
                         SCAN_ELEMS * (int)sizeof(int));

    // 1) prep: wfold + convert + count
    prep_kernel<<<prep_blocks, TPB>>>(x, W1, W2, a_src1, a_dst1, a_src2, a_dst2, ei,
                                      xh, W1h, W2h, was1, wad1, was2, wad2, cnt);
    // 2) scan (coalesced, zeroes cnt for next call)
    scan_kernel<<<1, 1024, SCAN_ELEMS * sizeof(int)>>>(cnt, rowptr, cursor);
    // 3) fused: gemm1 + scatter + alphas1
    fused3_kernel<<<G1_BLOCKS + SC_BLOCKS + AL_BLOCKS, TPB>>>(
        xh, W1h, h1h, ei, cursor, csrc, x, was1, wad1, as1, ad1);
    // 4) layer-1 aggregation (+ finalize + layer-2 logits)
    agg1_kernel<<<(N_NODES * 32 + TPB - 1) / TPB, TPB>>>(
        rowptr, csrc, as1, ad1, h1h, b1, was2, wad2, x2h, as2, ad2);
    // 5) gemm2
    dim3 g2(C / 64, (N_NODES + 127) / 128);
    hgemm_kernel<<<g2, TPB>>>(x2h, W2h, h2h, N_NODES, C);
    // 6) layer-2 aggregation + finalize
    agg2_kernel<<<(N_NODES * 32 + TPB - 1) / TPB, TPB>>>(
        rowptr, csrc, as2, ad2, h2h, b2, out);
}

// round 8
// speedup vs baseline: 3.2433x; 1.1051x over previous
#include <cuda_runtime.h>
#include <cuda_fp16.h>
#include <math.h>
#include <stdint.h>

#define N_NODES 20000
#define N_EDGES 640000
#define E_TOT   660000          // + self loops
#define H1      4
#define C       128
#define HC1     (H1 * C)        // 512

// ---------------- scratch (no allocations allowed) ----------------
__device__ __half g_xh[N_NODES * C];
__device__ __half g_W1h[C * HC1];
__device__ __half g_W2h[C * C];
__device__ __half g_h1h[N_NODES * HC1];
__device__ __half g_h2h[N_NODES * C];
__device__ __half g_x2h[N_NODES * C];
__device__ float  g_as1[N_NODES * H1];
__device__ float  g_ad1[N_NODES * H1];
__device__ float  g_as2[N_NODES];
__device__ float  g_ad2[N_NODES];
__device__ float  g_was1[C * H1];
__device__ float  g_wad1[C * H1];
__device__ float  g_was2[C];
__device__ float  g_wad2[C];
__device__ int    g_rowptr[N_NODES + 1];
__device__ int    g_cursor[N_NODES];
__device__ int    g_cnt[N_NODES];       // zero-initialized; scan re-zeroes after use
__device__ int    g_csrc[E_TOT + 1];    // +1 pad for unconditional prefetch

__device__ __forceinline__ unsigned int smem_u32(const void* p)
{
    return (unsigned int)__cvta_generic_to_shared(p);
}

__device__ __forceinline__ unsigned long long pack_f32x2(float lo, float hi)
{
    unsigned long long r;
    asm("mov.b64 %0, {%1, %2};" : "=l"(r) : "f"(lo), "f"(hi));
    return r;
}
__device__ __forceinline__ void unpack_f32x2(float& lo, float& hi, unsigned long long v)
{
    asm("mov.b64 {%0, %1}, %2;" : "=f"(lo), "=f"(hi) : "l"(v));
}
__device__ __forceinline__ unsigned long long fma_f32x2(
    unsigned long long a, unsigned long long b, unsigned long long c)
{
    unsigned long long d;
    asm("fma.rn.f32x2 %0, %1, %2, %3;" : "=l"(d) : "l"(a), "l"(b), "l"(c));
    return d;
}

// ================= prep: wfold + fp16 convert + degree count, one kernel =================
__global__ __launch_bounds__(256) void prep_kernel(
    const float* __restrict__ x,  const float* __restrict__ W1,
    const float* __restrict__ W2, const float* __restrict__ as1,
    const float* __restrict__ ad1, const float* __restrict__ as2,
    const float* __restrict__ ad2, const int* __restrict__ ei,
    __half* __restrict__ xh, __half* __restrict__ W1h, __half* __restrict__ W2h,
    float* __restrict__ w_as1, float* __restrict__ w_ad1,
    float* __restrict__ w_as2, float* __restrict__ w_ad2,
    int* __restrict__ cnt, int* __restrict__ csrc)
{
    const int NX4  = N_NODES * C / 4;
    const int NW14 = C * HC1 / 4;
    const int NW24 = C * C / 4;
    const int CONV_TOTAL = NX4 + NW14 + NW24;
    int gid = blockIdx.x * blockDim.x + threadIdx.x;

    if (gid == 0) csrc[E_TOT] = 0;      // init prefetch pad

    // --- fp32->fp16 convert ---
    if (gid < CONV_TOTAL) {
        const float* src; __half* dst; int j;
        if (gid < NX4) { src = x; dst = xh; j = gid; }
        else if (gid < NX4 + NW14) { src = W1; dst = W1h; j = gid - NX4; }
        else { src = W2; dst = W2h; j = gid - NX4 - NW14; }
        float4 v = ((const float4*)src)[j];
        __half2* d2 = (__half2*)(dst + (size_t)j * 4);
        d2[0] = __floats2half2_rn(v.x, v.y);
        d2[1] = __floats2half2_rn(v.z, v.w);
    }
    // --- degree count ---
    if (gid < E_TOT) {
        int d = (gid < N_EDGES) ? ei[N_EDGES + gid] : (gid - N_EDGES);
        atomicAdd(&cnt[d], 1);
    }
    // --- weight folding (first 640 warps) ---
    int w = gid >> 5, lane = gid & 31;
    if (w < 512) {
        int k = w >> 2, h = w & 3;
        float4 wv = *(const float4*)&W1[(size_t)k * HC1 + h * C + lane * 4];
        float4 av = *(const float4*)&as1[h * C + lane * 4];
        float4 dv = *(const float4*)&ad1[h * C + lane * 4];
        float ss = wv.x * av.x + wv.y * av.y + wv.z * av.z + wv.w * av.w;
        float sd = wv.x * dv.x + wv.y * dv.y + wv.z * dv.z + wv.w * dv.w;
#pragma unroll
        for (int off = 16; off > 0; off >>= 1) {
            ss += __shfl_down_sync(0xffffffff, ss, off);
            sd += __shfl_down_sync(0xffffffff, sd, off);
        }
        if (lane == 0) { w_as1[k * H1 + h] = ss; w_ad1[k * H1 + h] = sd; }
    } else if (w < 640) {
        int k = w - 512;
        float4 wv = *(const float4*)&W2[(size_t)k * C + lane * 4];
        float4 av = *(const float4*)&as2[lane * 4];
        float4 dv = *(const float4*)&ad2[lane * 4];
        float ss = wv.x * av.x + wv.y * av.y + wv.z * av.z + wv.w * av.w;
        float sd = wv.x * dv.x + wv.y * dv.y + wv.z * dv.z + wv.w * dv.w;
#pragma unroll
        for (int off = 16; off > 0; off >>= 1) {
            ss += __shfl_down_sync(0xffffffff, ss, off);
            sd += __shfl_down_sync(0xffffffff, sd, off);
        }
        if (lane == 0) { w_as2[k] = ss; w_ad2[k] = sd; }
    }
}

// ================= coalesced smem-staged scan (1 block); zeroes cnt afterward =================
#define SCAN_ELEMS 20480   // 1024 * 20
__global__ __launch_bounds__(1024) void scan_kernel(
    int* __restrict__ cnt, int* __restrict__ rowptr, int* __restrict__ cursor)
{
    extern __shared__ int sm[];           // SCAN_ELEMS ints = 80KB
    __shared__ int part[1024];
    const int t = threadIdx.x;
    const int CHUNK = 20;

    for (int i = t; i < SCAN_ELEMS; i += 1024)
        sm[i] = (i < N_NODES) ? cnt[i] : 0;
    __syncthreads();

    int base = t * CHUNK;
    int s = 0;
#pragma unroll
    for (int k = 0; k < CHUNK; k++) s += sm[base + k];
    part[t] = s;
    __syncthreads();
    for (int off = 1; off < 1024; off <<= 1) {
        int v = (t >= off) ? part[t - off] : 0;
        __syncthreads();
        part[t] += v;
        __syncthreads();
    }
    int run = part[t] - s;   // exclusive prefix of this thread's chunk
#pragma unroll
    for (int k = 0; k < CHUNK; k++) {
        int c = sm[base + k];
        sm[base + k] = run;   // replace with exclusive prefix
        run += c;
    }
    __syncthreads();
    for (int i = t; i < N_NODES; i += 1024) {
        int v = sm[i];
        rowptr[i] = v;
        cursor[i] = v;
        cnt[i] = 0;           // restore for next call
    }
    if (t == 1023) rowptr[N_NODES] = part[1023];
}

// ================= tensor-core GEMM body: C[M,N]=A[M,128]*B[128,N]; CTA 128x64, BK=64, 24KB smem =================
__device__ __forceinline__ void gemm_body(
    const __half* __restrict__ A, const __half* __restrict__ B,
    __half* __restrict__ Cmat, int M, int N, int bx, int by)
{
    __shared__ __half As[128][64];
    __shared__ __half Bs[64][64];

    const int tid = threadIdx.x;
    const int lane = tid & 31, wid = tid >> 5;
    const int warpM = wid >> 1, warpN = wid & 1;
    const int rowBase = by * 128;
    const int colBase = bx * 64;

    float acc[2][4][4];
#pragma unroll
    for (int mi = 0; mi < 2; mi++)
#pragma unroll
        for (int ni = 0; ni < 4; ni++)
#pragma unroll
            for (int q = 0; q < 4; q++) acc[mi][ni][q] = 0.f;

    const int arow0 = warpM * 32 + (lane & 15);
    const int brow0 = (lane & 15);
    const int hi = (lane >> 4);

#pragma unroll
    for (int kt = 0; kt < 2; kt++) {
#pragma unroll
        for (int i = tid; i < 1024; i += 256) {
            int r = i >> 3, ch = i & 7;
            int gr = rowBase + r;
            uint4 v = make_uint4(0u, 0u, 0u, 0u);
            if (gr < M) v = *(const uint4*)&A[(size_t)gr * 128 + kt * 64 + ch * 8];
            int sch = ch ^ (r & 7);
            *(uint4*)&As[r][sch * 8] = v;
        }
#pragma unroll
        for (int i = tid; i < 512; i += 256) {
            int r = i >> 3, ch = i & 7;
            uint4 v = *(const uint4*)&B[(size_t)(kt * 64 + r) * N + colBase + ch * 8];
            int sch = ch ^ (r & 7);
            *(uint4*)&Bs[r][sch * 8] = v;
        }
        __syncthreads();

#pragma unroll
        for (int kk = 0; kk < 4; kk++) {
            unsigned int a[2][4];
#pragma unroll
            for (int mi = 0; mi < 2; mi++) {
                int r = arow0 + mi * 16;
                int ch = (kk * 2 + hi) ^ (r & 7);
                unsigned int addr = smem_u32(&As[r][ch * 8]);
                asm volatile("ldmatrix.sync.aligned.m8n8.x4.shared.b16 {%0,%1,%2,%3}, [%4];"
                    : "=r"(a[mi][0]), "=r"(a[mi][1]), "=r"(a[mi][2]), "=r"(a[mi][3])
                    : "r"(addr));
            }
            unsigned int b[4][2];
#pragma unroll
            for (int np = 0; np < 2; np++) {
                int r = kk * 16 + brow0;
                int ch = (warpN * 4 + np * 2 + hi) ^ (r & 7);
                unsigned int addr = smem_u32(&Bs[r][ch * 8]);
                unsigned int r0, r1, r2, r3;
                asm volatile("ldmatrix.sync.aligned.m8n8.x4.trans.shared.b16 {%0,%1,%2,%3}, [%4];"
                    : "=r"(r0), "=r"(r1), "=r"(r2), "=r"(r3) : "r"(addr));
                b[np * 2][0] = r0;     b[np * 2][1] = r1;
                b[np * 2 + 1][0] = r2; b[np * 2 + 1][1] = r3;
            }
#pragma unroll
            for (int mi = 0; mi < 2; mi++)
#pragma unroll
                for (int ni = 0; ni < 4; ni++)
                    asm volatile(
                        "mma.sync.aligned.m16n8k16.row.col.f32.f16.f16.f32 "
                        "{%0,%1,%2,%3},{%4,%5,%6,%7},{%8,%9},{%0,%1,%2,%3};"
                        : "+f"(acc[mi][ni][0]), "+f"(acc[mi][ni][1]),
                          "+f"(acc[mi][ni][2]), "+f"(acc[mi][ni][3])
                        : "r"(a[mi][0]), "r"(a[mi][1]), "r"(a[mi][2]), "r"(a[mi][3]),
                          "r"(b[ni][0]), "r"(b[ni][1]));
        }
        __syncthreads();
    }

#pragma unroll
    for (int mi = 0; mi < 2; mi++) {
        int r0 = rowBase + warpM * 32 + mi * 16 + (lane >> 2);
#pragma unroll
        for (int ni = 0; ni < 4; ni++) {
            int cc = colBase + warpN * 32 + ni * 8 + (lane & 3) * 2;
            if (r0 < M)
                *(__half2*)&Cmat[(size_t)r0 * N + cc] =
                    __floats2half2_rn(acc[mi][ni][0], acc[mi][ni][1]);
            if (r0 + 8 < M)
                *(__half2*)&Cmat[(size_t)(r0 + 8) * N + cc] =
                    __floats2half2_rn(acc[mi][ni][2], acc[mi][ni][3]);
        }
    }
}

// ================= fused: gemm1 + CSR scatter + layer-1 logits =================
#define G1_BLOCKS  (8 * 157)
#define SC_BLOCKS  ((E_TOT + 255) / 256)
#define AL_BLOCKS  ((N_NODES * 32 + 255) / 256)
__global__ __launch_bounds__(256) void fused3_kernel(
    const __half* __restrict__ xh, const __half* __restrict__ W1h,
    __half* __restrict__ h1h,
    const int* __restrict__ ei, int* __restrict__ cursor, int* __restrict__ csrc,
    const float* __restrict__ x, const float* __restrict__ w_as1,
    const float* __restrict__ w_ad1, float* __restrict__ as_o,
    float* __restrict__ ad_o)
{
    int bid = blockIdx.x;
    if (bid < G1_BLOCKS) {
        gemm_body(xh, W1h, h1h, N_NODES, HC1, bid & 7, bid >> 3);
        return;
    }
    bid -= G1_BLOCKS;
    if (bid < SC_BLOCKS) {
        int i = bid * 256 + threadIdx.x;
        if (i < E_TOT) {
            int s, d;
            if (i < N_EDGES) { s = ei[i]; d = ei[N_EDGES + i]; }
            else { s = d = i - N_EDGES; }
            int pos = atomicAdd(&cursor[d], 1);
            csrc[pos] = s;
        }
        return;
    }
    bid -= SC_BLOCKS;
    {
        __shared__ float sw_s[C * H1], sw_d[C * H1];
        for (int i = threadIdx.x; i < C * H1; i += 256) {
            sw_s[i] = w_as1[i]; sw_d[i] = w_ad1[i];
        }
        __syncthreads();
        int n = (bid * 256 + threadIdx.x) >> 5;
        int lane = threadIdx.x & 31;
        if (n >= N_NODES) return;
        float4 xv = *(const float4*)&x[(size_t)n * C + lane * 4];
        float xs[4] = {xv.x, xv.y, xv.z, xv.w};
        float ps[4] = {0, 0, 0, 0}, pd[4] = {0, 0, 0, 0};
#pragma unroll
        for (int j = 0; j < 4; j++) {
            int k = lane * 4 + j;
#pragma unroll
            for (int h = 0; h < 4; h++) {
                ps[h] += xs[j] * sw_s[k * 4 + h];
                pd[h] += xs[j] * sw_d[k * 4 + h];
            }
        }
#pragma unroll
        for (int off = 16; off > 0; off >>= 1) {
#pragma unroll
            for (int h = 0; h < 4; h++) {
                ps[h] += __shfl_down_sync(0xffffffff, ps[h], off);
                pd[h] += __shfl_down_sync(0xffffffff, pd[h], off);
            }
        }
        if (lane == 0) {
            *(float4*)&as_o[n * 4] = make_float4(ps[0], ps[1], ps[2], ps[3]);
            *(float4*)&ad_o[n * 4] = make_float4(pd[0], pd[1], pd[2], pd[3]);
        }
    }
}

// ================= standalone GEMM kernel (layer 2) =================
__global__ __launch_bounds__(256) void hgemm_kernel(
    const __half* __restrict__ A, const __half* __restrict__ B,
    __half* __restrict__ Cmat, int M, int N)
{
    gemm_body(A, B, Cmat, M, N, blockIdx.x, blockIdx.y);
}

// ================= layer-1 aggregation: 2 logits/lane, f32x2 FMA, fused finalize + L2 logits =================
__global__ __launch_bounds__(256) void agg1_kernel(
    const int* __restrict__ rowptr, const int* __restrict__ csrc,
    const float* __restrict__ as_v, const float* __restrict__ ad_v,
    const __half* __restrict__ h1h, const float* __restrict__ b1,
    const float* __restrict__ w_as2, const float* __restrict__ w_ad2,
    __half* __restrict__ x2h, float* __restrict__ as2_o, float* __restrict__ ad2_o)
{
    __shared__ float sw_s[C], sw_d[C];
    for (int i = threadIdx.x; i < C; i += 256) { sw_s[i] = w_as2[i]; sw_d[i] = w_ad2[i]; }
    __syncthreads();
    int n = (blockIdx.x * 256 + threadIdx.x) >> 5;
    int lane = threadIdx.x & 31;
    if (n >= N_NODES) return;
    int start = rowptr[n], end = rowptr[n + 1];
    float4 adn = *(const float4*)&ad_v[n * 4];
    const int grp = lane >> 4;           // 0: heads 0/2, 1: heads 1/3
    const float ada = grp ? adn.y : adn.x;
    const float adb = grp ? adn.w : adn.z;

    unsigned long long accA2[4], accB2[4];
#pragma unroll
    for (int j = 0; j < 4; j++) { accA2[j] = 0ull; accB2[j] = 0ull; }
    float da = 0.f, db = 0.f;

    int sA = csrc[start];                // deg >= 1 (self loop)
    float4 lgA = *(const float4*)&as_v[sA * 4];
    for (int e = start; e < end; e++) {
        int s = sA; float4 lg = lgA;
        sA = csrc[e + 1];                // padded: always safe
        lgA = *(const float4*)&as_v[sA * 4];
        float la = (grp ? lg.y : lg.x) + ada; la = fmaxf(la, 0.2f * la);
        float lb = (grp ? lg.w : lg.z) + adb; lb = fmaxf(lb, 0.2f * lb);
        float pa = __expf(la), pb = __expf(lb);
        da += pa; db += pb;
        unsigned long long pa2 = pack_f32x2(pa, pa);
        unsigned long long pb2 = pack_f32x2(pb, pb);
        const uint4* row = (const uint4*)(h1h + (size_t)s * HC1);
        uint4 qa = row[lane];            // heads 0/1 region (this lane's 8 channels)
        uint4 qb = row[32 + lane];       // heads 2/3 region
        const __half2* ha = (const __half2*)&qa;
        const __half2* hb = (const __half2*)&qb;
#pragma unroll
        for (int j = 0; j < 4; j++) {
            float2 fa = __half22float2(ha[j]);
            float2 fb = __half22float2(hb[j]);
            accA2[j] = fma_f32x2(pack_f32x2(fa.x, fa.y), pa2, accA2[j]);
            accB2[j] = fma_f32x2(pack_f32x2(fb.x, fb.y), pb2, accB2[j]);
        }
    }
    float invA = 1.f / da;
    float invB = 1.f / db;
    const int sub = lane & 15;
    float4 bb0 = *(const float4*)&b1[sub * 8];
    float4 bb1 = *(const float4*)&b1[sub * 8 + 4];
    float bbar[8] = {bb0.x, bb0.y, bb0.z, bb0.w, bb1.x, bb1.y, bb1.z, bb1.w};

    float accA[8], accB[8];
#pragma unroll
    for (int j = 0; j < 4; j++) {
        unpack_f32x2(accA[2 * j], accA[2 * j + 1], accA2[j]);
        unpack_f32x2(accB[2 * j], accB[2 * j + 1], accB2[j]);
    }

    float v[8];
    __half hout[8];
#pragma unroll
    for (int j = 0; j < 8; j++) {
        float vA = accA[j] * invA;
        float vB = accB[j] * invB;
        vA += __shfl_xor_sync(0xffffffff, vA, 16);   // head0+head1
        vB += __shfl_xor_sync(0xffffffff, vB, 16);   // head2+head3
        float val = 0.25f * (vA + vB) + bbar[j];
        val = val > 0.f ? val : expm1f(val);
        v[j] = val;
        hout[j] = __float2half(val);
    }
    if (lane < 16)
        *(uint4*)&x2h[(size_t)n * C + sub * 8] = *(uint4*)hout;

    float ps = 0.f, pd = 0.f;
#pragma unroll
    for (int j = 0; j < 8; j++) {
        ps += v[j] * sw_s[sub * 8 + j];
        pd += v[j] * sw_d[sub * 8 + j];
    }
#pragma unroll
    for (int off = 16; off > 0; off >>= 1) {
        ps += __shfl_down_sync(0xffffffff, ps, off);
        pd += __shfl_down_sync(0xffffffff, pd, off);
    }
    if (lane == 0) { as2_o[n] = 0.5f * ps; ad2_o[n] = 0.5f * pd; }   // halves double-count
}

// ================= layer-2 aggregation + finalize =================
__global__ __launch_bounds__(256) void agg2_kernel(
    const int* __restrict__ rowptr, const int* __restrict__ csrc,
    const float* __restrict__ as_v, const float* __restrict__ ad_v,
    const __half* __restrict__ h2h, const float* __restrict__ b2,
    float* __restrict__ out)
{
    int n = (blockIdx.x * 256 + threadIdx.x) >> 5;
    int lane = threadIdx.x & 31;
    if (n >= N_NODES) return;
    int start = rowptr[n], end = rowptr[n + 1];
    float adn = ad_v[n];

    unsigned long long acc0 = 0ull, acc1 = 0ull;
    float den = 0.f;
    int sA = csrc[start];
    float lA = as_v[sA];
    for (int e = start; e < end; e++) {
        int s = sA; float l = lA;
        sA = csrc[e + 1];                // padded: always safe
        lA = as_v[sA];
        l += adn;
        l = fmaxf(l, 0.2f * l);
        float p = __expf(l);
        den += p;
        unsigned long long p2 = pack_f32x2(p, p);
        uint2 q = *(const uint2*)(h2h + (size_t)s * C + lane * 4);
        const __half2* h = (const __half2*)&q;
        float2 f0 = __half22float2(h[0]), f1 = __half22float2(h[1]);
        acc0 = fma_f32x2(pack_f32x2(f0.x, f0.y), p2, acc0);
        acc1 = fma_f32x2(pack_f32x2(f1.x, f1.y), p2, acc1);
    }
    float ax, ay, az, aw;
    unpack_f32x2(ax, ay, acc0);
    unpack_f32x2(az, aw, acc1);
    float inv = 1.f / den;
    float4 bb = *(const float4*)&b2[lane * 4];
    float v0 = ax * inv + bb.x;
    float v1 = ay * inv + bb.y;
    float v2 = az * inv + bb.z;
    float v3 = aw * inv + bb.w;
    v0 = v0 > 0.f ? v0 : expm1f(v0);
    v1 = v1 > 0.f ? v1 : expm1f(v1);
    v2 = v2 > 0.f ? v2 : expm1f(v2);
    v3 = v3 > 0.f ? v3 : expm1f(v3);
    *(float4*)&out[(size_t)n * C + lane * 4] = make_float4(v0, v1, v2, v3);
}

// ---------------- launch ----------------
extern "C" void kernel_launch(void* const* d_in, const int* in_sizes, int n_in,
                              void* d_out, int out_size)
{
    const float* x      = (const float*)d_in[0];
    const float* W1     = (const float*)d_in[1];
    const float* a_src1 = (const float*)d_in[2];
    const float* a_dst1 = (const float*)d_in[3];
    const float* b1     = (const float*)d_in[4];
    const float* W2     = (const float*)d_in[5];
    const float* a_src2 = (const float*)d_in[6];
    const float* a_dst2 = (const float*)d_in[7];
    const float* b2     = (const float*)d_in[8];
    const int*   ei     = (const int*)d_in[9];
    float* out = (float*)d_out;

    __half *xh, *W1h, *W2h, *h1h, *h2h, *x2h;
    float *as1, *ad1, *as2, *ad2, *was1, *wad1, *was2, *wad2;
    int *rowptr, *cursor, *cnt, *csrc;
    cudaGetSymbolAddress((void**)&xh,     g_xh);
    cudaGetSymbolAddress((void**)&W1h,    g_W1h);
    cudaGetSymbolAddress((void**)&W2h,    g_W2h);
    cudaGetSymbolAddress((void**)&h1h,    g_h1h);
    cudaGetSymbolAddress((void**)&h2h,    g_h2h);
    cudaGetSymbolAddress((void**)&x2h,    g_x2h);
    cudaGetSymbolAddress((void**)&as1,    g_as1);
    cudaGetSymbolAddress((void**)&ad1,    g_ad1);
    cudaGetSymbolAddress((void**)&as2,    g_as2);
    cudaGetSymbolAddress((void**)&ad2,    g_ad2);
    cudaGetSymbolAddress((void**)&was1,   g_was1);
    cudaGetSymbolAddress((void**)&wad1,   g_wad1);
    cudaGetSymbolAddress((void**)&was2,   g_was2);
    cudaGetSymbolAddress((void**)&wad2,   g_wad2);
    cudaGetSymbolAddress((void**)&rowptr, g_rowptr);
    cudaGetSymbolAddress((void**)&cursor, g_cursor);
    cudaGetSymbolAddress((void**)&cnt,    g_cnt);
    cudaGetSymbolAddress((void**)&csrc,   g_csrc);

    const int TPB = 256;
    const int CONV_TOTAL = (N_NODES * C + C * HC1 + C * C) / 4;
    int prep_blocks = (CONV_TOTAL + TPB - 1) / TPB;
    if (prep_blocks < (E_TOT + TPB - 1) / TPB) prep_blocks = (E_TOT + TPB - 1) / TPB;

    cudaFuncSetAttribute(scan_kernel, cudaFuncAttributeMaxDynamicSharedMemorySize,
                         SCAN_ELEMS * (int)sizeof(int));

    // 1) prep: wfold + convert + count (+ csrc pad init)
    prep_kernel<<<prep_blocks, TPB>>>(x, W1, W2, a_src1, a_dst1, a_src2, a_dst2, ei,
                                      xh, W1h, W2h, was1, wad1, was2, wad2, cnt, csrc);
    // 2) scan (coalesced, zeroes cnt for next call)
    scan_kernel<<<1, 1024, SCAN_ELEMS * sizeof(int)>>>(cnt, rowptr, cursor);
    // 3) fused: gemm1 + scatter + alphas1
    fused3_kernel<<<G1_BLOCKS + SC_BLOCKS + AL_BLOCKS, TPB>>>(
        xh, W1h, h1h, ei, cursor, csrc, x, was1, wad1, as1, ad1);
    // 4) layer-1 aggregation (+ finalize + layer-2 logits)
    agg1_kernel<<<(N_NODES * 32 + TPB - 1) / TPB, TPB>>>(
        rowptr, csrc, as1, ad1, h1h, b1, was2, wad2, x2h, as2, ad2);
    // 5) gemm2
    dim3 g2(C / 64, (N_NODES + 127) / 128);
    hgemm_kernel<<<g2, TPB>>>(x2h, W2h, h2h, N_NODES, C);
    // 6) layer-2 aggregation + finalize
    agg2_kernel<<<(N_NODES * 32 + TPB - 1) / TPB, TPB>>>(
        rowptr, csrc, as2, ad2, h2h, b2, out);
}

// round 9
// speedup vs baseline: 3.4110x; 1.0517x over previous
#include <cuda_runtime.h>
#include <cuda_fp16.h>
#include <math.h>
#include <stdint.h>

#define N_NODES 20000
#define N_EDGES 640000
#define E_TOT   660000          // + self loops
#define H1      4
#define C       128
#define HC1     (H1 * C)        // 512

// ---------------- scratch (no allocations allowed) ----------------
__device__ __half g_xh[N_NODES * C];
__device__ __half g_W1s[HC1 * C];        // stacked+scaled: [512 x 128]
__device__ __half g_W2h[C * C];
__device__ __half g_yh[N_NODES * HC1];   // per-head aggregated x (normalized), fp16
__device__ __half g_x2h[N_NODES * C];
__device__ __half g_y2h[N_NODES * C];
__device__ float  g_as1[N_NODES * H1];
__device__ float  g_ad1[N_NODES * H1];
__device__ float  g_as2[N_NODES];
__device__ float  g_ad2[N_NODES];
__device__ float  g_was1[C * H1];
__device__ float  g_wad1[C * H1];
__device__ float  g_was2[C];
__device__ float  g_wad2[C];
__device__ int    g_rowptr[N_NODES + 1];
__device__ int    g_cursor[N_NODES];
__device__ int    g_cnt[N_NODES];       // zero-initialized; scan re-zeroes after use
__device__ int    g_csrc[E_TOT + 1];    // +1 pad for unconditional prefetch

__device__ __forceinline__ unsigned int smem_u32(const void* p)
{
    return (unsigned int)__cvta_generic_to_shared(p);
}

// ================= prep: wfold + fp16 converts (x, W1s stacked, W2) + degree count =================
__global__ __launch_bounds__(256) void prep_kernel(
    const float* __restrict__ x,  const float* __restrict__ W1,
    const float* __restrict__ W2, const float* __restrict__ as1,
    const float* __restrict__ ad1, const float* __restrict__ as2,
    const float* __restrict__ ad2, const int* __restrict__ ei,
    __half* __restrict__ xh, __half* __restrict__ W1s, __half* __restrict__ W2h,
    float* __restrict__ w_as1, float* __restrict__ w_ad1,
    float* __restrict__ w_as2, float* __restrict__ w_ad2,
    int* __restrict__ cnt, int* __restrict__ csrc)
{
    const int R0 = N_NODES * C / 4;      // 640000  x -> xh
    const int R1 = HC1 * C / 4;          // 16384   W1 -> W1s (transposed blocks, 0.25x)
    const int R2 = C * C / 4;            // 4096    W2 -> W2h
    int gid = blockIdx.x * blockDim.x + threadIdx.x;

    if (gid == 0) csrc[E_TOT] = 0;      // prefetch pad

    if (gid < R0) {
        float4 v = ((const float4*)x)[gid];
        __half2* d2 = (__half2*)(xh + (size_t)gid * 4);
        d2[0] = __floats2half2_rn(v.x, v.y);
        d2[1] = __floats2half2_rn(v.z, v.w);
    } else if (gid < R0 + R1) {
        int m = gid - R0;
        int r = m >> 5;                  // row of W1s: 0..511
        int jc = (m & 31) * 4;           // col
        int h = r >> 7, i = r & 127;
        float4 v = *(const float4*)&W1[(size_t)i * HC1 + h * C + jc];
        __half2* d2 = (__half2*)(W1s + (size_t)r * C + jc);
        d2[0] = __floats2half2_rn(0.25f * v.x, 0.25f * v.y);
        d2[1] = __floats2half2_rn(0.25f * v.z, 0.25f * v.w);
    } else if (gid < R0 + R1 + R2) {
        int m = gid - R0 - R1;
        float4 v = ((const float4*)W2)[m];
        __half2* d2 = (__half2*)(W2h + (size_t)m * 4);
        d2[0] = __floats2half2_rn(v.x, v.y);
        d2[1] = __floats2half2_rn(v.z, v.w);
    }
    if (gid < E_TOT) {
        int d = (gid < N_EDGES) ? ei[N_EDGES + gid] : (gid - N_EDGES);
        atomicAdd(&cnt[d], 1);
    }
    int w = gid >> 5, lane = gid & 31;
    if (w < 512) {
        int k = w >> 2, h = w & 3;
        float4 wv = *(const float4*)&W1[(size_t)k * HC1 + h * C + lane * 4];
        float4 av = *(const float4*)&as1[h * C + lane * 4];
        float4 dv = *(const float4*)&ad1[h * C + lane * 4];
        float ss = wv.x * av.x + wv.y * av.y + wv.z * av.z + wv.w * av.w;
        float sd = wv.x * dv.x + wv.y * dv.y + wv.z * dv.z + wv.w * dv.w;
#pragma unroll
        for (int off = 16; off > 0; off >>= 1) {
            ss += __shfl_down_sync(0xffffffff, ss, off);
            sd += __shfl_down_sync(0xffffffff, sd, off);
        }
        if (lane == 0) { w_as1[k * H1 + h] = ss; w_ad1[k * H1 + h] = sd; }
    } else if (w < 640) {
        int k = w - 512;
        float4 wv = *(const float4*)&W2[(size_t)k * C + lane * 4];
        float4 av = *(const float4*)&as2[lane * 4];
        float4 dv = *(const float4*)&ad2[lane * 4];
        float ss = wv.x * av.x + wv.y * av.y + wv.z * av.z + wv.w * av.w;
        float sd = wv.x * dv.x + wv.y * dv.y + wv.z * dv.z + wv.w * dv.w;
#pragma unroll
        for (int off = 16; off > 0; off >>= 1) {
            ss += __shfl_down_sync(0xffffffff, ss, off);
            sd += __shfl_down_sync(0xffffffff, sd, off);
        }
        if (lane == 0) { w_as2[k] = ss; w_ad2[k] = sd; }
    }
}

// ================= coalesced smem-staged scan (1 block); zeroes cnt afterward =================
#define SCAN_ELEMS 20480   // 1024 * 20
__global__ __launch_bounds__(1024) void scan_kernel(
    int* __restrict__ cnt, int* __restrict__ rowptr, int* __restrict__ cursor)
{
    extern __shared__ int sm[];
    __shared__ int part[1024];
    const int t = threadIdx.x;
    const int CHUNK = 20;

    for (int i = t; i < SCAN_ELEMS; i += 1024)
        sm[i] = (i < N_NODES) ? cnt[i] : 0;
    __syncthreads();

    int base = t * CHUNK;
    int s = 0;
#pragma unroll
    for (int k = 0; k < CHUNK; k++) s += sm[base + k];
    part[t] = s;
    __syncthreads();
    for (int off = 1; off < 1024; off <<= 1) {
        int v = (t >= off) ? part[t - off] : 0;
        __syncthreads();
        part[t] += v;
        __syncthreads();
    }
    int run = part[t] - s;
#pragma unroll
    for (int k = 0; k < CHUNK; k++) {
        int c = sm[base + k];
        sm[base + k] = run;
        run += c;
    }
    __syncthreads();
    for (int i = t; i < N_NODES; i += 1024) {
        int v = sm[i];
        rowptr[i] = v;
        cursor[i] = v;
        cnt[i] = 0;
    }
    if (t == 1023) rowptr[N_NODES] = part[1023];
}

// ================= fused: CSR scatter + layer-1 logits =================
#define SC_BLOCKS  ((E_TOT + 255) / 256)
#define AL_BLOCKS  ((N_NODES * 32 + 255) / 256)
__global__ __launch_bounds__(256) void fused_sa_kernel(
    const int* __restrict__ ei, int* __restrict__ cursor, int* __restrict__ csrc,
    const float* __restrict__ x, const float* __restrict__ w_as1,
    const float* __restrict__ w_ad1, float* __restrict__ as_o,
    float* __restrict__ ad_o)
{
    int bid = blockIdx.x;
    if (bid < SC_BLOCKS) {
        int i = bid * 256 + threadIdx.x;
        if (i < E_TOT) {
            int s, d;
            if (i < N_EDGES) { s = ei[i]; d = ei[N_EDGES + i]; }
            else { s = d = i - N_EDGES; }
            int pos = atomicAdd(&cursor[d], 1);
            csrc[pos] = s;
        }
        return;
    }
    bid -= SC_BLOCKS;
    {
        __shared__ float sw_s[C * H1], sw_d[C * H1];
        for (int i = threadIdx.x; i < C * H1; i += 256) {
            sw_s[i] = w_as1[i]; sw_d[i] = w_ad1[i];
        }
        __syncthreads();
        int n = (bid * 256 + threadIdx.x) >> 5;
        int lane = threadIdx.x & 31;
        if (n >= N_NODES) return;
        float4 xv = *(const float4*)&x[(size_t)n * C + lane * 4];
        float xs[4] = {xv.x, xv.y, xv.z, xv.w};
        float ps[4] = {0, 0, 0, 0}, pd[4] = {0, 0, 0, 0};
#pragma unroll
        for (int j = 0; j < 4; j++) {
            int k = lane * 4 + j;
#pragma unroll
            for (int h = 0; h < 4; h++) {
                ps[h] += xs[j] * sw_s[k * 4 + h];
                pd[h] += xs[j] * sw_d[k * 4 + h];
            }
        }
#pragma unroll
        for (int off = 16; off > 0; off >>= 1) {
#pragma unroll
            for (int h = 0; h < 4; h++) {
                ps[h] += __shfl_down_sync(0xffffffff, ps[h], off);
                pd[h] += __shfl_down_sync(0xffffffff, pd[h], off);
            }
        }
        if (lane == 0) {
            *(float4*)&as_o[n * 4] = make_float4(ps[0], ps[1], ps[2], ps[3]);
            *(float4*)&ad_o[n * 4] = make_float4(pd[0], pd[1], pd[2], pd[3]);
        }
    }
}

// ================= layer-1 aggregation of x: 4 heads, gather 128ch only =================
__global__ __launch_bounds__(256) void agg1_kernel(
    const int* __restrict__ rowptr, const int* __restrict__ csrc,
    const float* __restrict__ as_v, const float* __restrict__ ad_v,
    const __half* __restrict__ xh, __half* __restrict__ yh)
{
    int n = (blockIdx.x * 256 + threadIdx.x) >> 5;
    int lane = threadIdx.x & 31;
    if (n >= N_NODES) return;
    int start = rowptr[n], end = rowptr[n + 1];
    float4 adn = *(const float4*)&ad_v[n * 4];
    const int grp = lane >> 4;           // 0: heads 0/1, 1: heads 2/3
    const int sub = lane & 15;
    const float adP = grp ? adn.z : adn.x;
    const float adQ = grp ? adn.w : adn.y;

    float accP[8], accQ[8];
#pragma unroll
    for (int j = 0; j < 8; j++) { accP[j] = 0.f; accQ[j] = 0.f; }
    float dP = 0.f, dQ = 0.f;

    int sA = csrc[start];                // deg >= 1 (self loop)
    float4 lgA = *(const float4*)&as_v[sA * 4];
    for (int e = start; e < end; e++) {
        int s = sA; float4 lg = lgA;
        sA = csrc[e + 1];
        lgA = *(const float4*)&as_v[sA * 4];
        float lP = (grp ? lg.z : lg.x) + adP; lP = fmaxf(lP, 0.2f * lP);
        float lQ = (grp ? lg.w : lg.y) + adQ; lQ = fmaxf(lQ, 0.2f * lQ);
        float pP = __expf(lP), pQ = __expf(lQ);
        dP += pP; dQ += pQ;
        uint4 q = *(const uint4*)(xh + (size_t)s * C + sub * 8);
        const __half2* h = (const __half2*)&q;
#pragma unroll
        for (int j = 0; j < 4; j++) {
            float2 f = __half22float2(h[j]);
            accP[2*j]   += pP * f.x; accP[2*j+1] += pP * f.y;
            accQ[2*j]   += pQ * f.x; accQ[2*j+1] += pQ * f.y;
        }
    }
    float invP = 1.f / dP, invQ = 1.f / dQ;
    __half hP[8], hQ[8];
#pragma unroll
    for (int j = 0; j < 8; j++) {
        hP[j] = __float2half(accP[j] * invP);
        hQ[j] = __float2half(accQ[j] * invQ);
    }
    // heads: grp*2 (P), grp*2+1 (Q)
    *(uint4*)&yh[(size_t)n * HC1 + (grp * 2) * C + sub * 8]     = *(uint4*)hP;
    *(uint4*)&yh[(size_t)n * HC1 + (grp * 2 + 1) * C + sub * 8] = *(uint4*)hQ;
}

// ================= tensor-core GEMM + bias + ELU (+ optional layer-2 logits) =================
// C[M,128] = A[M,KDIM] * B[KDIM,128]; CTA 128x128, BK=64, 8 warps (4M x 2N)
template <int KDIM, bool OUT_HALF, bool DO_LOGITS>
__global__ __launch_bounds__(256) void gemm_bias_elu_kernel(
    const __half* __restrict__ A, const __half* __restrict__ B,
    const float* __restrict__ bias, void* __restrict__ Cout, int M,
    const float* __restrict__ w_s, const float* __restrict__ w_d,
    float* __restrict__ as_o, float* __restrict__ ad_o)
{
    __shared__ __half As[128][64];
    __shared__ __half Bs[64][128];
    __shared__ float sw_s[DO_LOGITS ? C : 1], sw_d[DO_LOGITS ? C : 1];
    __shared__ float redS[DO_LOGITS ? 128 : 1][2], redD[DO_LOGITS ? 128 : 1][2];

    const int tid = threadIdx.x;
    const int lane = tid & 31, wid = tid >> 5;
    const int warpM = wid >> 1, warpN = wid & 1;
    const int rowBase = blockIdx.x * 128;

    if (DO_LOGITS) {
        for (int i = tid; i < C; i += 256) { sw_s[i] = w_s[i]; sw_d[i] = w_d[i]; }
    }

    float acc[2][8][4];
#pragma unroll
    for (int mi = 0; mi < 2; mi++)
#pragma unroll
        for (int ni = 0; ni < 8; ni++)
#pragma unroll
            for (int q = 0; q < 4; q++) acc[mi][ni][q] = 0.f;

    const int arow0 = warpM * 32 + (lane & 15);
    const int brow0 = (lane & 15);
    const int hi = (lane >> 4);

    for (int kt = 0; kt < KDIM / 64; kt++) {
        // A tile: 128 rows x 8 chunks of 8 halfs
#pragma unroll
        for (int i = tid; i < 1024; i += 256) {
            int r = i >> 3, ch = i & 7;
            int gr = rowBase + r;
            uint4 v = make_uint4(0u, 0u, 0u, 0u);
            if (gr < M) v = *(const uint4*)&A[(size_t)gr * KDIM + kt * 64 + ch * 8];
            int sch = ch ^ (r & 7);
            *(uint4*)&As[r][sch * 8] = v;
        }
        // B tile: 64 rows x 16 chunks
#pragma unroll
        for (int i = tid; i < 1024; i += 256) {
            int r = i >> 4, ch = i & 15;
            uint4 v = *(const uint4*)&B[(size_t)(kt * 64 + r) * C + ch * 8];
            int sch = (ch & 8) | ((ch & 7) ^ (r & 7));
            *(uint4*)&Bs[r][sch * 8] = v;
        }
        __syncthreads();

#pragma unroll
        for (int kk = 0; kk < 4; kk++) {
            unsigned int a[2][4];
#pragma unroll
            for (int mi = 0; mi < 2; mi++) {
                int r = arow0 + mi * 16;
                int ch = (kk * 2 + hi) ^ (r & 7);
                unsigned int addr = smem_u32(&As[r][ch * 8]);
                asm volatile("ldmatrix.sync.aligned.m8n8.x4.shared.b16 {%0,%1,%2,%3}, [%4];"
                    : "=r"(a[mi][0]), "=r"(a[mi][1]), "=r"(a[mi][2]), "=r"(a[mi][3])
                    : "r"(addr));
            }
            unsigned int b[8][2];
#pragma unroll
            for (int np = 0; np < 4; np++) {
                int r = kk * 16 + brow0;
                int chL = warpN * 8 + np * 2 + hi;          // logical chunk 0..15
                int ch = (chL & 8) | ((chL & 7) ^ (r & 7)); // stored (swizzled)
                unsigned int addr = smem_u32(&Bs[r][ch * 8]);
                unsigned int r0, r1, r2, r3;
                asm volatile("ldmatrix.sync.aligned.m8n8.x4.trans.shared.b16 {%0,%1,%2,%3}, [%4];"
                    : "=r"(r0), "=r"(r1), "=r"(r2), "=r"(r3) : "r"(addr));
                b[np * 2][0] = r0;     b[np * 2][1] = r1;
                b[np * 2 + 1][0] = r2; b[np * 2 + 1][1] = r3;
            }
#pragma unroll
            for (int mi = 0; mi < 2; mi++)
#pragma unroll
                for (int ni = 0; ni < 8; ni++)
                    asm volatile(
                        "mma.sync.aligned.m16n8k16.row.col.f32.f16.f16.f32 "
                        "{%0,%1,%2,%3},{%4,%5,%6,%7},{%8,%9},{%0,%1,%2,%3};"
                        : "+f"(acc[mi][ni][0]), "+f"(acc[mi][ni][1]),
                          "+f"(acc[mi][ni][2]), "+f"(acc[mi][ni][3])
                        : "r"(a[mi][0]), "r"(a[mi][1]), "r"(a[mi][2]), "r"(a[mi][3]),
                          "r"(b[ni][0]), "r"(b[ni][1]));
        }
        __syncthreads();
    }

    // ---- epilogue: bias + ELU (+ logits) ----
    float psum[2][2], pdum[2][2];
    if (DO_LOGITS) {
        psum[0][0] = psum[0][1] = psum[1][0] = psum[1][1] = 0.f;
        pdum[0][0] = pdum[0][1] = pdum[1][0] = pdum[1][1] = 0.f;
    }
#pragma unroll
    for (int mi = 0; mi < 2; mi++) {
        int r0 = rowBase + warpM * 32 + mi * 16 + (lane >> 2);
#pragma unroll
        for (int ni = 0; ni < 8; ni++) {
            int col = warpN * 64 + ni * 8 + (lane & 3) * 2;
            float b0 = bias[col], b1v = bias[col + 1];
            float v0 = acc[mi][ni][0] + b0;  v0 = v0 > 0.f ? v0 : expm1f(v0);
            float v1 = acc[mi][ni][1] + b1v; v1 = v1 > 0.f ? v1 : expm1f(v1);
            float v2 = acc[mi][ni][2] + b0;  v2 = v2 > 0.f ? v2 : expm1f(v2);
            float v3 = acc[mi][ni][3] + b1v; v3 = v3 > 0.f ? v3 : expm1f(v3);
            if (DO_LOGITS) {
                psum[mi][0] += v0 * sw_s[col] + v1 * sw_s[col + 1];
                psum[mi][1] += v2 * sw_s[col] + v3 * sw_s[col + 1];
                pdum[mi][0] += v0 * sw_d[col] + v1 * sw_d[col + 1];
                pdum[mi][1] += v2 * sw_d[col] + v3 * sw_d[col + 1];
            }
            if (OUT_HALF) {
                __half* Ch = (__half*)Cout;
                if (r0 < M)
                    *(__half2*)&Ch[(size_t)r0 * C + col] = __floats2half2_rn(v0, v1);
                if (r0 + 8 < M)
                    *(__half2*)&Ch[(size_t)(r0 + 8) * C + col] = __floats2half2_rn(v2, v3);
            } else {
                float* Cf = (float*)Cout;
                if (r0 < M)
                    *(float2*)&Cf[(size_t)r0 * C + col] = make_float2(v0, v1);
                if (r0 + 8 < M)
                    *(float2*)&Cf[(size_t)(r0 + 8) * C + col] = make_float2(v2, v3);
            }
        }
    }
    if (DO_LOGITS) {
        // reduce over the 4 lanes sharing a row (lane&3)
#pragma unroll
        for (int mi = 0; mi < 2; mi++)
#pragma unroll
            for (int rh = 0; rh < 2; rh++) {
                float s = psum[mi][rh], d = pdum[mi][rh];
                s += __shfl_xor_sync(0xffffffff, s, 1);
                s += __shfl_xor_sync(0xffffffff, s, 2);
                d += __shfl_xor_sync(0xffffffff, d, 1);
                d += __shfl_xor_sync(0xffffffff, d, 2);
                if ((lane & 3) == 0) {
                    int lr = warpM * 32 + mi * 16 + rh * 8 + (lane >> 2);
                    redS[lr][warpN] = s;
                    redD[lr][warpN] = d;
                }
            }
        __syncthreads();
        if (tid < 128) {
            int rg = rowBase + tid;
            if (rg < M) {
                as_o[rg] = redS[tid][0] + redS[tid][1];
                ad_o[rg] = redD[tid][0] + redD[tid][1];
            }
        }
    }
}

// ================= layer-2 aggregation of x2 (normalized) -> y2 fp16 =================
__global__ __launch_bounds__(256) void agg2_kernel(
    const int* __restrict__ rowptr, const int* __restrict__ csrc,
    const float* __restrict__ as_v, const float* __restrict__ ad_v,
    const __half* __restrict__ x2h, __half* __restrict__ y2h)
{
    int n = (blockIdx.x * 256 + threadIdx.x) >> 5;
    int lane = threadIdx.x & 31;
    if (n >= N_NODES) return;
    int start = rowptr[n], end = rowptr[n + 1];
    float adn = ad_v[n];

    float ax = 0.f, ay = 0.f, az = 0.f, aw = 0.f, den = 0.f;
    int sA = csrc[start];
    float lA = as_v[sA];
    for (int e = start; e < end; e++) {
        int s = sA; float l = lA;
        sA = csrc[e + 1];
        lA = as_v[sA];
        l += adn;
        l = fmaxf(l, 0.2f * l);
        float p = __expf(l);
        den += p;
        uint2 q = *(const uint2*)(x2h + (size_t)s * C + lane * 4);
        const __half2* h = (const __half2*)&q;
        float2 f0 = __half22float2(h[0]), f1 = __half22float2(h[1]);
        ax += p * f0.x; ay += p * f0.y; az += p * f1.x; aw += p * f1.y;
    }
    float inv = 1.f / den;
    __half2 o0 = __floats2half2_rn(ax * inv, ay * inv);
    __half2 o1 = __floats2half2_rn(az * inv, aw * inv);
    uint2 o; o.x = *(unsigned int*)&o0; o.y = *(unsigned int*)&o1;
    *(uint2*)&y2h[(size_t)n * C + lane * 4] = o;
}

// ---------------- launch ----------------
extern "C" void kernel_launch(void* const* d_in, const int* in_sizes, int n_in,
                              void* d_out, int out_size)
{
    const float* x      = (const float*)d_in[0];
    const float* W1     = (const float*)d_in[1];
    const float* a_src1 = (const float*)d_in[2];
    const float* a_dst1 = (const float*)d_in[3];
    const float* b1     = (const float*)d_in[4];
    const float* W2     = (const float*)d_in[5];
    const float* a_src2 = (const float*)d_in[6];
    const float* a_dst2 = (const float*)d_in[7];
    const float* b2     = (const float*)d_in[8];
    const int*   ei     = (const int*)d_in[9];
    float* out = (float*)d_out;

    __half *xh, *W1s, *W2h, *yh, *x2h, *y2h;
    float *as1, *ad1, *as2, *ad2, *was1, *wad1, *was2, *wad2;
    int *rowptr, *cursor, *cnt, *csrc;
    cudaGetSymbolAddress((void**)&xh,     g_xh);
    cudaGetSymbolAddress((void**)&W1s,    g_W1s);
    cudaGetSymbolAddress((void**)&W2h,    g_W2h);
    cudaGetSymbolAddress((void**)&yh,     g_yh);
    cudaGetSymbolAddress((void**)&x2h,    g_x2h);
    cudaGetSymbolAddress((void**)&y2h,    g_y2h);
    cudaGetSymbolAddress((void**)&as1,    g_as1);
    cudaGetSymbolAddress((void**)&ad1,    g_ad1);
    cudaGetSymbolAddress((void**)&as2,    g_as2);
    cudaGetSymbolAddress((void**)&ad2,    g_ad2);
    cudaGetSymbolAddress((void**)&was1,   g_was1);
    cudaGetSymbolAddress((void**)&wad1,   g_wad1);
    cudaGetSymbolAddress((void**)&was2,   g_was2);
    cudaGetSymbolAddress((void**)&wad2,   g_wad2);
    cudaGetSymbolAddress((void**)&rowptr, g_rowptr);
    cudaGetSymbolAddress((void**)&cursor, g_cursor);
    cudaGetSymbolAddress((void**)&cnt,    g_cnt);
    cudaGetSymbolAddress((void**)&csrc,   g_csrc);

    const int TPB = 256;
    const int PREP_TOTAL = N_NODES * C / 4 + HC1 * C / 4 + C * C / 4;   // 660480
    int prep_blocks = (PREP_TOTAL + TPB - 1) / TPB;
    if (prep_blocks < (E_TOT + TPB - 1) / TPB) prep_blocks = (E_TOT + TPB - 1) / TPB;

    cudaFuncSetAttribute(scan_kernel, cudaFuncAttributeMaxDynamicSharedMemorySize,
                         SCAN_ELEMS * (int)sizeof(int));

    const int GEMM_GRID = (N_NODES + 127) / 128;   // 157

    // 1) prep: wfold + converts + count (+ csrc pad)
    prep_kernel<<<prep_blocks, TPB>>>(x, W1, W2, a_src1, a_dst1, a_src2, a_dst2, ei,
                                      xh, W1s, W2h, was1, wad1, was2, wad2, cnt, csrc);
    // 2) scan
    scan_kernel<<<1, 1024, SCAN_ELEMS * sizeof(int)>>>(cnt, rowptr, cursor);
    // 3) fused: scatter + alphas1
    fused_sa_kernel<<<SC_BLOCKS + AL_BLOCKS, TPB>>>(
        ei, cursor, csrc, x, was1, wad1, as1, ad1);
    // 4) layer-1 aggregation of x -> yh
    agg1_kernel<<<(N_NODES * 32 + TPB - 1) / TPB, TPB>>>(
        rowptr, csrc, as1, ad1, xh, yh);
    // 5) gemm-mid: x2 = ELU(yh * W1s + b1); epilogue computes layer-2 logits
    gemm_bias_elu_kernel<HC1, true, true><<<GEMM_GRID, TPB>>>(
        yh, W1s, b1, x2h, N_NODES, was2, wad2, as2, ad2);
    // 6) layer-2 aggregation of x2 -> y2
    agg2_kernel<<<(N_NODES * 32 + TPB - 1) / TPB, TPB>>>(
        rowptr, csrc, as2, ad2, x2h, y2h);
    // 7) gemm-out: out = ELU(y2 * W2 + b2)
    gemm_bias_elu_kernel<C, false, false><<<GEMM_GRID, TPB>>>(
        y2h, W2h, b2, out, N_NODES, (const float*)nullptr, (const float*)nullptr,
        (float*)nullptr, (float*)nullptr);
}